// round 9
// baseline (speedup 1.0000x reference)
#include <cuda_runtime.h>
#include <math.h>

#define BSZ    256
#define PRIOR  60
#define FRAMES 240
#define POSE   768
#define PRED   180
#define CHUNK  10
#define EPSBN  1e-5f

// ---------------------------------------------------------------------------
// Scratch (static device globals)
// ---------------------------------------------------------------------------
__device__ float g_p1  [BSZ * PRED * POSE];
__device__ float g_p   [BSZ * PRED * POSE];
__device__ float g_xr  [BSZ * PRIOR * POSE];
__device__ float g_wr1 [3 * 192 * 64];
__device__ float g_wr2 [3 * 192 * 192];
__device__ float g_w1cat[2 * POSE * CHUNK * POSE];
__device__ float g_sw2 [POSE * POSE];
__device__ float g_tw2 [POSE * POSE];
__device__ float g_pw2 [POSE * POSE];
__device__ float g_pw1T[POSE * POSE];
__device__ float g_Wc  [POSE * POSE];
__device__ float g_bc  [POSE];
__device__ float g_Wt  [CHUNK * CHUNK * POSE];
__device__ float g_bt  [CHUNK];
__device__ float g_hsp [BSZ * POSE];
__device__ float g_htm [BSZ * POSE];
__device__ float g_mem [BSZ * POSE];
__device__ float g_mem2[BSZ * POSE];
__device__ float g_penc[BSZ * CHUNK];
__device__ float g_Mmat[POSE * CHUNK];
__device__ float g_part[24 * 256 * 1536];

__device__ __forceinline__ float warp_sum(float v) {
    #pragma unroll
    for (int o = 16; o; o >>= 1) v += __shfl_xor_sync(0xffffffffu, v, o);
    return v;
}
__device__ __forceinline__ unsigned f2tf(float x) {
    unsigned u;
    asm("cvt.rna.tf32.f32 %0, %1;" : "=r"(u) : "f"(x));
    return u;
}
__device__ __forceinline__ float rnd(float x) { return __uint_as_float(f2tf(x)); }

// cp.async helpers
__device__ __forceinline__ void cp16(unsigned d, const void* s, bool p) {
    asm volatile("cp.async.ca.shared.global [%0], [%1], 16, %2;"
                 :: "r"(d), "l"(s), "r"(p ? 16 : 0));
}
#define CP_COMMIT() asm volatile("cp.async.commit_group;" ::: "memory")
#define CP_WAIT1()  asm volatile("cp.async.wait_group 1;" ::: "memory")
#define CP_WAIT2()  asm volatile("cp.async.wait_group 2;" ::: "memory")

__device__ __forceinline__ void ldsm4(unsigned &r0, unsigned &r1, unsigned &r2, unsigned &r3,
                                      unsigned addr)
{
    asm volatile("ldmatrix.sync.aligned.m8n8.x4.shared.b16 {%0,%1,%2,%3}, [%4];"
                 : "=r"(r0), "=r"(r1), "=r"(r2), "=r"(r3) : "r"(addr));
}

#define MMA_TF32(acc, a, b0v, b1v) \
    asm volatile( \
        "mma.sync.aligned.m16n8k8.row.col.f32.tf32.tf32.f32 " \
        "{%0,%1,%2,%3},{%4,%5,%6,%7},{%8,%9},{%0,%1,%2,%3};" \
        : "+f"((acc)[0]), "+f"((acc)[1]), "+f"((acc)[2]), "+f"((acc)[3]) \
        : "r"((a)[0]), "r"((a)[1]), "r"((a)[2]), "r"((a)[3]), \
          "r"(b0v), "r"(b1v))

// One BK=16 slab, MT x 4 warp tile (64x32-class kernels)
template<int MT>
__device__ __forceinline__ void mma_slab(unsigned aA, unsigned aB, float acc[MT][4][4])
{
    #pragma unroll
    for (int ks = 0; ks < 16; ks += 8) {
        unsigned a[MT][4], b[2][4];
        #pragma unroll
        for (int mt = 0; mt < MT; mt++)
            ldsm4(a[mt][0], a[mt][1], a[mt][2], a[mt][3], aA + (mt * 16 * 20 + ks) * 4);
        #pragma unroll
        for (int np = 0; np < 2; np++)
            ldsm4(b[np][0], b[np][1], b[np][2], b[np][3], aB + (np * 16 * 20 + ks) * 4);
        #pragma unroll
        for (int mt = 0; mt < MT; mt++)
            #pragma unroll
            for (int nt = 0; nt < 4; nt++)
                MMA_TF32(acc[mt][nt], a[mt],
                         b[nt >> 1][(nt & 1) * 2], b[nt >> 1][(nt & 1) * 2 + 1]);
    }
}

// ---------------------------------------------------------------------------
// Generic tf32 GEMM, B [N,K] row-major, 128x128 tile, 4-stage, split-K.
// ---------------------------------------------------------------------------
__global__ __launch_bounds__(256, 2)
void gemm_bt_ms(const float* __restrict__ A, long lda,
                const float* __restrict__ B, long ldb,
                float* __restrict__ Cpart,
                int M, int N, int K, int kchunk, int ldcN, int coffs)
{
    extern __shared__ unsigned sh[];
    unsigned shbase;
    asm("{ .reg .u64 t; cvta.to.shared.u64 t, %1; cvt.u32.u64 %0, t; }"
        : "=r"(shbase) : "l"((void*)sh));
    const unsigned STG = 128u * 20u * 4u;
    const unsigned bsoff = 4u * STG;

    const int tid = threadIdx.x;
    const int warpid = tid >> 5, lane = tid & 31;
    const int mbase = (warpid >> 2) * 64, nbase = (warpid & 3) * 32;
    const int quad = lane >> 3, qr = lane & 7;
    const int bm = blockIdx.y * 128, bn = blockIdx.x * 128;
    const int k0base = blockIdx.z * kchunk;
    const int kend = min(k0base + kchunk, K);
    const int nk = (kend - k0base) >> 4;

    const unsigned aAq = shbase + (((mbase + (quad & 1) * 8 + qr) * 20 + (quad >> 1) * 4) * 4);
    const unsigned aBq = shbase + bsoff + (((nbase + (quad >> 1) * 8 + qr) * 20 + (quad & 1) * 4) * 4);

    float acc[4][4][4];
    #pragma unroll
    for (int mt = 0; mt < 4; mt++)
        #pragma unroll
        for (int nt = 0; nt < 4; nt++)
            #pragma unroll
            for (int r = 0; r < 4; r++) acc[mt][nt][r] = 0.f;

    const int m_ = tid >> 2, kq = tid & 3;
    auto load = [&](int st, int k0) {
        #pragma unroll
        for (int i = 0; i < 2; i++) {
            int m = m_ + i * 64;
            int gk = k0 + kq * 4;
            unsigned da = shbase + st * STG + (m * 20 + kq * 4) * 4;
            cp16(da, A + (long)(bm + m) * lda + gk, bm + m < M);
            unsigned db = shbase + bsoff + st * STG + (m * 20 + kq * 4) * 4;
            cp16(db, B + (long)(bn + m) * ldb + gk, bn + m < N);
        }
    };

    #pragma unroll
    for (int s = 0; s < 3; s++) {
        if (s < nk) load(s, k0base + s * 16);
        CP_COMMIT();
    }
    for (int i = 0; i < nk; i++) {
        CP_WAIT2();
        __syncthreads();
        if (i + 3 < nk) load((i + 3) & 3, k0base + (i + 3) * 16);
        CP_COMMIT();
        int st = i & 3;
        mma_slab<4>(aAq + st * STG, aBq + st * STG, acc);
    }

    float* Cz = Cpart + (long)blockIdx.z * M * ldcN;
    #pragma unroll
    for (int mt = 0; mt < 4; mt++) {
        int gm0 = bm + mbase + mt * 16 + (lane >> 2);
        #pragma unroll
        for (int nt = 0; nt < 4; nt++) {
            int gn0 = bn + nbase + nt * 8 + (lane & 3) * 2;
            if (gm0 < M && gn0 < N) {
                Cz[(long)gm0 * ldcN + coffs + gn0]     = acc[mt][nt][0];
                Cz[(long)gm0 * ldcN + coffs + gn0 + 1] = acc[mt][nt][1];
            }
            if (gm0 + 8 < M && gn0 < N) {
                Cz[(long)(gm0 + 8) * ldcN + coffs + gn0]     = acc[mt][nt][2];
                Cz[(long)(gm0 + 8) * ldcN + coffs + gn0 + 1] = acc[mt][nt][3];
            }
        }
    }
}

// ---------------------------------------------------------------------------
// Tap-decomposed Conv1d(k=3,p=1), CTA 96x128, 3-stage. (unchanged from R7)
// ---------------------------------------------------------------------------
template<int ICH>
__global__ __launch_bounds__(256, 2)
void conv_tap(const float* __restrict__ X,
              const float* __restrict__ Wr,
              const float* __restrict__ cb,
              const float* __restrict__ bg, const float* __restrict__ bb,
              const float* __restrict__ bmn, const float* __restrict__ bv,
              float* __restrict__ Out)
{
    constexpr int ICHP = (ICH + 63) & ~63;
    constexpr int NK = ICHP / 16;
    extern __shared__ unsigned sh[];
    unsigned shbase;
    asm("{ .reg .u64 t; cvta.to.shared.u64 t, %1; cvt.u32.u64 %0, t; }"
        : "=r"(shbase) : "l"((void*)sh));
    const unsigned ASTG = 288u * 20u * 4u;
    const unsigned BSTG = 16u * 136u * 4u;
    const unsigned bsoff = 3u * ASTG;

    const int b = blockIdx.z;
    const float* Xb = X + (long)b * ICH * POSE;
    const int tid = threadIdx.x;
    const int warpid = tid >> 5, lane = tid & 31;
    const int mbase = (warpid >> 2) * 48, nbase = (warpid & 3) * 32;
    const int quad = lane >> 3, qr = lane & 7;
    const int gid = lane >> 2, tig = lane & 3;
    const int bm = blockIdx.y * 96, bn = blockIdx.x * 128;

    const unsigned aAq = shbase + (((mbase + (quad & 1) * 8 + qr) * 20 + (quad >> 1) * 4) * 4);
    const int bBq = (int)(bsoff >> 2) + tig * 136 + 3 + nbase + gid;

    float acc[3][4][4];
    #pragma unroll
    for (int mt = 0; mt < 3; mt++)
        #pragma unroll
        for (int nt = 0; nt < 4; nt++)
            #pragma unroll
            for (int r = 0; r < 4; r++) acc[mt][nt][r] = 0.f;

    auto load = [&](int st, int k0) {
        #pragma unroll
        for (int i = 0; i < 5; i++) {
            int f = tid + i * 256;
            if (f < 1152) {
                int tap = f / 384, rem = f - tap * 384;
                int m = rem >> 2, kq = rem & 3;
                unsigned da = shbase + st * ASTG + ((tap * 96 + m) * 20 + kq * 4) * 4;
                cp16(da, Wr + ((long)tap * 192 + bm + m) * ICHP + k0 + kq * 4, true);
            }
        }
        #pragma unroll
        for (int i = 0; i < 3; i++) {
            int f = tid + i * 256;
            if (f < 544) {
                int kk = f / 34, j = f - kk * 34;
                int pos0 = bn - 4 + j * 4;
                bool p = (k0 + kk < ICH) && (pos0 >= 0) && (pos0 < POSE);
                unsigned db = shbase + bsoff + st * BSTG + (kk * 136 + j * 4) * 4;
                cp16(db, Xb + (long)(k0 + kk) * POSE + pos0, p);
            }
        }
    };

    #pragma unroll
    for (int s = 0; s < 2; s++) {
        if (s < NK) load(s, s * 16);
        CP_COMMIT();
    }
    const unsigned* shu = sh;
    for (int i = 0; i < NK; i++) {
        CP_WAIT1();
        __syncthreads();
        if (i + 2 < NK) load((i + 2) % 3, (i + 2) * 16);
        CP_COMMIT();
        int st = i % 3;
        unsigned aA = aAq + st * ASTG;
        int bB = bBq + st * (int)(BSTG >> 2);
        #pragma unroll
        for (int t = 0; t < 3; t++) {
            #pragma unroll
            for (int ks = 0; ks < 16; ks += 8) {
                unsigned a[3][4];
                #pragma unroll
                for (int mt = 0; mt < 3; mt++)
                    ldsm4(a[mt][0], a[mt][1], a[mt][2], a[mt][3],
                          aA + ((t * 96 + mt * 16) * 20 + ks) * 4);
                #pragma unroll
                for (int nt = 0; nt < 4; nt++) {
                    unsigned b0 = shu[bB + ks * 136 + t + nt * 8];
                    unsigned b1 = shu[bB + (ks + 4) * 136 + t + nt * 8];
                    #pragma unroll
                    for (int mt = 0; mt < 3; mt++)
                        MMA_TF32(acc[mt][nt], a[mt], b0, b1);
                }
            }
        }
    }

    #pragma unroll
    for (int mt = 0; mt < 3; mt++) {
        #pragma unroll
        for (int half = 0; half < 2; half++) {
            int gm = bm + mbase + mt * 16 + (lane >> 2) + half * 8;
            if (gm < PRED) {
                float s  = bg[gm] * rsqrtf(bv[gm] + EPSBN);
                float sht = bb[gm] - bmn[gm] * s;
                float cv = cb[gm];
                #pragma unroll
                for (int nt = 0; nt < 4; nt++) {
                    int gn0 = bn + nbase + nt * 8 + (lane & 3) * 2;
                    float y0 = fmaxf(acc[mt][nt][half * 2]     + cv, 0.f);
                    float y1 = fmaxf(acc[mt][nt][half * 2 + 1] + cv, 0.f);
                    Out[((long)b * PRED + gm) * POSE + gn0]     = rnd(y0 * s + sht);
                    Out[((long)b * PRED + gm) * POSE + gn0 + 1] = rnd(y1 * s + sht);
                }
            }
        }
    }
}

// ---------------------------------------------------------------------------
// Final fused GEMM, BIG TILE: CTA 128x256, warp tile 64x64 (8 warps),
// 4-stage cp.async, 1 CTA/SM. out = concat(x_r, p) @ Wc^T + bc.
// ---------------------------------------------------------------------------
__global__ __launch_bounds__(256)
void final_big(const float* __restrict__ x, const float* __restrict__ p,
               const float* __restrict__ Wm, const float* __restrict__ bias,
               float* __restrict__ C)
{
    extern __shared__ unsigned sh[];
    __shared__ const float* rowp[128];
    unsigned shbase;
    asm("{ .reg .u64 t; cvta.to.shared.u64 t, %1; cvt.u32.u64 %0, t; }"
        : "=r"(shbase) : "l"((void*)sh));
    const unsigned ASTG = 128u * 20u * 4u;   // 10240
    const unsigned BSTG = 256u * 20u * 4u;   // 20480
    const unsigned bsoff = 4u * ASTG;        // 40960

    const int tid = threadIdx.x;
    const int warpid = tid >> 5, lane = tid & 31;
    const int mbase = (warpid >> 2) * 64, nbase = (warpid & 3) * 64;
    const int quad = lane >> 3, qr = lane & 7;
    const int bm = blockIdx.y * 128, bn = blockIdx.x * 256;
    const int nk = POSE / 16;  // 48

    if (tid < 128) {
        int r = bm + tid;
        int bb_ = r / FRAMES;
        int f = r - bb_ * FRAMES;
        rowp[tid] = (f < PRIOR) ? x + ((long)bb_ * PRIOR + f) * POSE
                                : p + ((long)bb_ * PRED + (f - PRIOR)) * POSE;
    }
    __syncthreads();

    const unsigned aAq = shbase + (((mbase + (quad & 1) * 8 + qr) * 20 + (quad >> 1) * 4) * 4);
    const unsigned aBq = shbase + bsoff + (((nbase + (quad >> 1) * 8 + qr) * 20 + (quad & 1) * 4) * 4);

    float acc[4][8][4];
    #pragma unroll
    for (int mt = 0; mt < 4; mt++)
        #pragma unroll
        for (int nt = 0; nt < 8; nt++)
            #pragma unroll
            for (int r = 0; r < 4; r++) acc[mt][nt][r] = 0.f;

    const int m_ = tid >> 2, kq = tid & 3;
    auto load = [&](int st, int k0) {
        int gk = k0 + kq * 4;
        #pragma unroll
        for (int i = 0; i < 2; i++) {
            int m = m_ + i * 64;
            unsigned da = shbase + st * ASTG + (m * 20 + kq * 4) * 4;
            cp16(da, rowp[m] + gk, true);
        }
        #pragma unroll
        for (int i = 0; i < 4; i++) {
            int n = m_ + i * 64;
            unsigned db = shbase + bsoff + st * BSTG + (n * 20 + kq * 4) * 4;
            cp16(db, Wm + (long)(bn + n) * POSE + gk, true);
        }
    };

    #pragma unroll
    for (int s = 0; s < 3; s++) { load(s, s * 16); CP_COMMIT(); }
    for (int i = 0; i < nk; i++) {
        CP_WAIT2();
        __syncthreads();
        if (i + 3 < nk) load((i + 3) & 3, (i + 3) * 16);
        CP_COMMIT();
        int st = i & 3;
        unsigned aA = aAq + st * ASTG, aB = aBq + st * BSTG;
        #pragma unroll
        for (int ks = 0; ks < 16; ks += 8) {
            unsigned a[4][4], b[4][4];
            #pragma unroll
            for (int mt = 0; mt < 4; mt++)
                ldsm4(a[mt][0], a[mt][1], a[mt][2], a[mt][3], aA + (mt * 16 * 20 + ks) * 4);
            #pragma unroll
            for (int np = 0; np < 4; np++)
                ldsm4(b[np][0], b[np][1], b[np][2], b[np][3], aB + (np * 16 * 20 + ks) * 4);
            #pragma unroll
            for (int mt = 0; mt < 4; mt++)
                #pragma unroll
                for (int nt = 0; nt < 8; nt++)
                    MMA_TF32(acc[mt][nt], a[mt],
                             b[nt >> 1][(nt & 1) * 2], b[nt >> 1][(nt & 1) * 2 + 1]);
        }
    }

    #pragma unroll
    for (int mt = 0; mt < 4; mt++) {
        int gm0 = bm + mbase + mt * 16 + (lane >> 2);
        #pragma unroll
        for (int nt = 0; nt < 8; nt++) {
            int gn0 = bn + nbase + nt * 8 + (lane & 3) * 2;
            float2 bv = *(const float2*)(bias + gn0);
            float2 v0 = make_float2(acc[mt][nt][0] + bv.x, acc[mt][nt][1] + bv.y);
            float2 v1 = make_float2(acc[mt][nt][2] + bv.x, acc[mt][nt][3] + bv.y);
            *(float2*)(C + (long)gm0 * POSE + gn0)       = v0;
            *(float2*)(C + (long)(gm0 + 8) * POSE + gn0) = v1;
        }
    }
}

// ---------------------------------------------------------------------------
// Prep + reduce + glue kernels
// ---------------------------------------------------------------------------
struct R8 { const float4* s[8]; float4* d[8]; int n4[8]; };
__global__ void k_round8(R8 r, int total4)
{
    int gid = blockIdx.x * blockDim.x + threadIdx.x;
    if (gid >= total4) return;
    #pragma unroll
    for (int k = 0; k < 8; k++) {
        if (gid < r.n4[k]) {
            float4 v = r.s[k][gid];
            r.d[k][gid] = make_float4(rnd(v.x), rnd(v.y), rnd(v.z), rnd(v.w));
            return;
        }
        gid -= r.n4[k];
    }
}

__global__ void k_convw(const float* __restrict__ w1, const float* __restrict__ w2,
                        float* __restrict__ Wr1, float* __restrict__ Wr2)
{
    const int N1 = 3 * 192 * 64, N2 = 3 * 192 * 192;
    int t = blockIdx.x * blockDim.x + threadIdx.x;
    if (t < N1) {
        int tap = t / (192 * 64), rem = t % (192 * 64);
        int o = rem / 64, ich = rem % 64;
        float v = 0.f;
        if (o < PRED && ich < PRIOR) v = rnd(w1[(o * PRIOR + ich) * 3 + tap]);
        Wr1[t] = v;
    } else if (t < N1 + N2) {
        t -= N1;
        int tap = t / (192 * 192), rem = t % (192 * 192);
        int o = rem / 192, ich = rem % 192;
        float v = 0.f;
        if (o < PRED && ich < PRED) v = rnd(w2[(o * PRED + ich) * 3 + tap]);
        Wr2[t] = v;
    }
}

__global__ void k_trT(const float* __restrict__ s, float* __restrict__ d)
{
    __shared__ float t[32][33];
    int x0 = blockIdx.x * 32, y0 = blockIdx.y * 32;
    for (int i = threadIdx.y; i < 32; i += 8)
        t[i][threadIdx.x] = s[(long)(y0 + i) * POSE + x0 + threadIdx.x];
    __syncthreads();
    for (int i = threadIdx.y; i < 32; i += 8)
        d[(long)(x0 + i) * POSE + y0 + threadIdx.x] = rnd(t[threadIdx.x][i]);
}

__global__ void reduce2(const float* __restrict__ part, int S,
                        const float* __restrict__ ba, const float* __restrict__ bb,
                        float* __restrict__ oa, float* __restrict__ ob, int doRound)
{
    const int MN = BSZ * 1536;
    int i = blockIdx.x * blockDim.x + threadIdx.x;
    if (i >= MN) return;
    float s = 0.f;
    for (int z = 0; z < S; z++) s += part[(long)z * MN + i];
    int m = i / 1536, n = i - m * 1536;
    float* o; int nn;
    if (n < 768) { o = oa; nn = n; s += ba[n]; }
    else         { o = ob; nn = n - 768; s += bb[nn]; }
    o[m * 768 + nn] = doRound ? rnd(s) : s;
}

__global__ void reduce_round(const float* __restrict__ part,
                             float* __restrict__ C, int MN, int S)
{
    int i = blockIdx.x * blockDim.x + threadIdx.x;
    if (i >= MN) return;
    float s = 0.f;
    for (int z = 0; z < S; z++) s += part[(long)z * MN + i];
    C[i] = rnd(s);
}

__global__ void k_bc(const float* __restrict__ w2, const float* __restrict__ b1,
                     const float* __restrict__ b2, float* __restrict__ bc)
{
    int w = (blockIdx.x * blockDim.x + threadIdx.x) >> 5;
    int lane = threadIdx.x & 31;
    if (w >= POSE) return;
    float s = 0.f;
    for (int m = lane; m < POSE; m += 32) s += w2[(long)w * POSE + m] * b1[m];
    s = warp_sum(s);
    if (lane == 0) bc[w] = s + b2[w];
}

__global__ void k_tmm(const float* __restrict__ w1, const float* __restrict__ b1,
                      const float* __restrict__ w2, const float* __restrict__ b2,
                      float* __restrict__ Wt, float* __restrict__ bt)
{
    int idx = blockIdx.x * blockDim.x + threadIdx.x;
    const int KK = CHUNK * POSE;
    if (idx < CHUNK * KK) {
        int c = idx / KK, k = idx - c * KK;
        float s = 0.f;
        #pragma unroll
        for (int m = 0; m < CHUNK; m++) s += w2[c * CHUNK + m] * w1[(long)m * KK + k];
        Wt[idx] = s;
    }
    if (idx < CHUNK) {
        float s = b2[idx];
        #pragma unroll
        for (int m = 0; m < CHUNK; m++) s += w2[idx * CHUNK + m] * b1[m];
        bt[idx] = s;
    }
}

__global__ __launch_bounds__(320)
void gate_penc(float* __restrict__ p, const float* __restrict__ mem,
               const float* __restrict__ Wt, const float* __restrict__ bt,
               float* __restrict__ penc)
{
    __shared__ float sm[POSE];
    __shared__ float chunk[CHUNK * POSE];
    __shared__ float sig[CHUNK];
    const int b = blockIdx.x, t = threadIdx.x;
    float* pb = p + (long)b * PRED * POSE;

    for (int i = t; i < POSE; i += 320) sm[i] = mem[(long)b * POSE + i];
    for (int i = t; i < CHUNK * POSE; i += 320) chunk[i] = pb[i];
    __syncthreads();

    const int w = t >> 5, lane = t & 31;
    float s = 0.f;
    for (int d = lane; d < POSE; d += 32) s += sm[d] * chunk[w * POSE + d];
    s = warp_sum(s);
    if (lane == 0) sig[w] = 1.f / (1.f + expf(-s));
    __syncthreads();

    for (int i = t; i < CHUNK * POSE; i += 320) {
        int c = i / POSE, d = i - c * POSE;
        float g = sig[c];
        chunk[i] = g * chunk[i] + (1.f - g) * sm[d];
    }
    __syncthreads();
    for (int i = t; i < CHUNK * POSE; i += 320) pb[i] = rnd(chunk[i]);

    float acc = 0.f;
    for (int k = lane; k < CHUNK * POSE; k += 32) acc += chunk[k] * Wt[(long)w * CHUNK * POSE + k];
    acc = warp_sum(acc);
    if (lane == 0) penc[b * CHUNK + w] = acc + bt[w];
}

__global__ void k_M(const float* __restrict__ mem2, const float* __restrict__ penc,
                    float* __restrict__ Mo)
{
    __shared__ float pe[BSZ * CHUNK];
    const int t = threadIdx.x;
    for (int i = t; i < BSZ * CHUNK; i += 256) pe[i] = penc[i];
    __syncthreads();
    int d = blockIdx.x * 256 + t;
    float acc[CHUNK];
    #pragma unroll
    for (int c = 0; c < CHUNK; c++) acc[c] = 0.f;
    for (int b = 0; b < BSZ; b++) {
        float mv = mem2[(long)b * POSE + d];
        #pragma unroll
        for (int c = 0; c < CHUNK; c++) acc[c] = fmaf(mv, pe[b * CHUNK + c], acc[c]);
    }
    #pragma unroll
    for (int c = 0; c < CHUNK; c++) Mo[d * CHUNK + c] = acc[c];
}

__global__ __launch_bounds__(320)
void k_score2(float* __restrict__ p, const float* __restrict__ mem2,
              const float* __restrict__ Mo)
{
    __shared__ float sm[POSE];
    __shared__ float sc[CHUNK];
    __shared__ float softs[CHUNK];
    const int b = blockIdx.x, t = threadIdx.x;
    for (int i = t; i < POSE; i += 320) sm[i] = mem2[(long)b * POSE + i];
    __syncthreads();
    const int w = t >> 5, lane = t & 31;
    float s = 0.f;
    for (int d = lane; d < POSE; d += 32) s += sm[d] * Mo[d * CHUNK + w];
    s = warp_sum(s);
    if (lane == 0) sc[w] = s;
    __syncthreads();
    if (t == 0) {
        float mx = sc[0];
        #pragma unroll
        for (int c = 1; c < CHUNK; c++) mx = fmaxf(mx, sc[c]);
        float ssum = 0.f;
        #pragma unroll
        for (int c = 0; c < CHUNK; c++) { float e = expf(sc[c] - mx); softs[c] = e; ssum += e; }
        float inv = 1.f / ssum;
        #pragma unroll
        for (int c = 0; c < CHUNK; c++) softs[c] *= inv;
    }
    __syncthreads();
    float* pb = p + (long)b * PRED * POSE;
    for (int i = t; i < CHUNK * POSE; i += 320) {
        int c = i / POSE;
        pb[i] = rnd(pb[i] * (1.f + softs[c]));
    }
}

// ---------------------------------------------------------------------------
// Launch
// ---------------------------------------------------------------------------
extern "C" void kernel_launch(void* const* d_in, const int* in_sizes, int n_in,
                              void* d_out, int out_size)
{
    const float* x       = (const float*)d_in[0];
    const float* conv1_w = (const float*)d_in[1];
    const float* conv1_b = (const float*)d_in[2];
    const float* bn1_g   = (const float*)d_in[3];
    const float* bn1_b   = (const float*)d_in[4];
    const float* bn1_m   = (const float*)d_in[5];
    const float* bn1_v   = (const float*)d_in[6];
    const float* conv2_w = (const float*)d_in[7];
    const float* conv2_b = (const float*)d_in[8];
    const float* bn2_g   = (const float*)d_in[9];
    const float* bn2_b   = (const float*)d_in[10];
    const float* bn2_m   = (const float*)d_in[11];
    const float* bn2_v   = (const float*)d_in[12];
    const float* sp_w1   = (const float*)d_in[13];
    const float* sp_b1   = (const float*)d_in[14];
    const float* sp_w2   = (const float*)d_in[15];
    const float* sp_b2   = (const float*)d_in[16];
    const float* tmc_w1  = (const float*)d_in[17];
    const float* tmc_b1  = (const float*)d_in[18];
    const float* tmc_w2  = (const float*)d_in[19];
    const float* tmc_b2  = (const float*)d_in[20];
    const float* tmm_w1  = (const float*)d_in[21];
    const float* tmm_b1  = (const float*)d_in[22];
    const float* tmm_w2  = (const float*)d_in[23];
    const float* tmm_b2  = (const float*)d_in[24];
    const float* post_w1 = (const float*)d_in[25];
    const float* post_b1 = (const float*)d_in[26];
    const float* post_w2 = (const float*)d_in[27];
    const float* post_b2 = (const float*)d_in[28];

    float *p1, *p, *xr, *wr1, *wr2, *w1cat, *sw2, *tw2, *pw2, *pw1T;
    float *Wc, *bc, *Wt, *bt, *hsp, *htm, *mem, *mem2, *penc, *Mm, *part;
    cudaGetSymbolAddress((void**)&p1,    g_p1);
    cudaGetSymbolAddress((void**)&p,     g_p);
    cudaGetSymbolAddress((void**)&xr,    g_xr);
    cudaGetSymbolAddress((void**)&wr1,   g_wr1);
    cudaGetSymbolAddress((void**)&wr2,   g_wr2);
    cudaGetSymbolAddress((void**)&w1cat, g_w1cat);
    cudaGetSymbolAddress((void**)&sw2,   g_sw2);
    cudaGetSymbolAddress((void**)&tw2,   g_tw2);
    cudaGetSymbolAddress((void**)&pw2,   g_pw2);
    cudaGetSymbolAddress((void**)&pw1T,  g_pw1T);
    cudaGetSymbolAddress((void**)&Wc,    g_Wc);
    cudaGetSymbolAddress((void**)&bc,    g_bc);
    cudaGetSymbolAddress((void**)&Wt,    g_Wt);
    cudaGetSymbolAddress((void**)&bt,    g_bt);
    cudaGetSymbolAddress((void**)&hsp,   g_hsp);
    cudaGetSymbolAddress((void**)&htm,   g_htm);
    cudaGetSymbolAddress((void**)&mem,   g_mem);
    cudaGetSymbolAddress((void**)&mem2,  g_mem2);
    cudaGetSymbolAddress((void**)&penc,  g_penc);
    cudaGetSymbolAddress((void**)&Mm,    g_Mmat);
    cudaGetSymbolAddress((void**)&part,  g_part);

    const int SMEM_GEMM  = 4 * 128 * 20 * 4 * 2;                 // 81920
    const int SMEM_CONV  = 3 * (288 * 20 + 16 * 136) * 4;        // 95232
    const int SMEM_FINAL = 4 * (128 + 256) * 20 * 4;             // 122880
    cudaFuncSetAttribute(gemm_bt_ms,    cudaFuncAttributeMaxDynamicSharedMemorySize, SMEM_GEMM);
    cudaFuncSetAttribute(final_big,     cudaFuncAttributeMaxDynamicSharedMemorySize, SMEM_FINAL);
    cudaFuncSetAttribute(conv_tap<60>,  cudaFuncAttributeMaxDynamicSharedMemorySize, SMEM_CONV);
    cudaFuncSetAttribute(conv_tap<180>, cudaFuncAttributeMaxDynamicSharedMemorySize, SMEM_CONV);

    // 0: round-copy tf32 GEMM inputs
    R8 r;
    const float* srcs[8] = { x, sp_w1, tmc_w1, sp_w2, tmc_w2, post_w2, x, x };
    float* dsts[8]       = { xr, w1cat, w1cat + POSE * CHUNK * POSE, sw2, tw2, pw2, xr, xr };
    int ns[8] = { BSZ*PRIOR*POSE, POSE*CHUNK*POSE, POSE*CHUNK*POSE,
                  POSE*POSE, POSE*POSE, POSE*POSE, 0, 0 };
    int total4 = 0;
    for (int i = 0; i < 8; i++) {
        r.s[i] = (const float4*)srcs[i]; r.d[i] = (float4*)dsts[i];
        r.n4[i] = ns[i] / 4; total4 += ns[i] / 4;
    }
    k_round8<<<(total4 + 255) / 256, 256>>>(r, total4);

    // 1: conv weight rearrangement
    k_convw<<<(3*192*64 + 3*192*192 + 255) / 256, 256>>>(conv1_w, conv2_w, wr1, wr2);

    // 2: conv1   3: conv2 (ncu capture = launch index 3)
    conv_tap<60><<<dim3(6, 2, BSZ), 256, SMEM_CONV>>>(xr, wr1, conv1_b,
                                                      bn1_g, bn1_b, bn1_m, bn1_v, p1);
    conv_tap<180><<<dim3(6, 2, BSZ), 256, SMEM_CONV>>>(p1, wr2, conv2_b,
                                                       bn2_g, bn2_b, bn2_m, bn2_v, p);

    // 4-6: small weight prep
    k_trT<<<dim3(24, 24), dim3(32, 8)>>>(post_w1, pw1T);
    k_bc<<<96, 256>>>(post_w2, post_b1, post_b2, bc);
    k_tmm<<<300, 256>>>(tmm_w1, tmm_b1, tmm_w2, tmm_b2, Wt, bt);

    // tail = x_r[:, 50:60, :] flattened
    const float* tail = xr + (PRIOR - CHUNK) * POSE;
    // 7,8: merged layer-1 of SP & TMC (single GEMM, N=1536, split-K 16)
    gemm_bt_ms<<<dim3(12, 2, 16), 256, SMEM_GEMM>>>(tail, (long)PRIOR * POSE, w1cat,
        (long)CHUNK * POSE, part, BSZ, 2 * POSE, CHUNK * POSE, 480, 1536, 0);
    reduce2<<<(BSZ * 1536 + 255) / 256, 256>>>(part, 16, sp_b1, tmc_b1, hsp, htm, 1);
    // 9-11: layer-2
    gemm_bt_ms<<<dim3(6, 2, 8), 256, SMEM_GEMM>>>(hsp, POSE, sw2, POSE,
        part, BSZ, POSE, POSE, 96, 1536, 0);
    gemm_bt_ms<<<dim3(6, 2, 8), 256, SMEM_GEMM>>>(htm, POSE, tw2, POSE,
        part, BSZ, POSE, POSE, 96, 1536, 768);
    reduce2<<<(BSZ * 1536 + 255) / 256, 256>>>(part, 8, sp_b2, tmc_b2, mem, mem2, 0);

    // 12,13: Wc = post_w2 @ post_w1 (tf32)
    gemm_bt_ms<<<dim3(6, 6, 8), 256, SMEM_GEMM>>>(pw2, POSE, pw1T, POSE,
        part, POSE, POSE, POSE, 96, POSE, 0);
    reduce_round<<<(POSE * POSE + 255) / 256, 256>>>(part, Wc, POSE * POSE, 8);

    // 14-16: memory nets
    gate_penc<<<BSZ, 320>>>(p, mem, Wt, bt, penc);
    k_M<<<3, 256>>>(mem2, penc, Mm);
    k_score2<<<BSZ, 320>>>(p, mem2, Mm);

    // 17: final collapsed post-header GEMM (big tile) -> d_out
    final_big<<<dim3(3, 480), 256, SMEM_FINAL>>>(xr, p, Wc, bc, (float*)d_out);
}

// round 11
// speedup vs baseline: 1.1949x; 1.1949x over previous
#include <cuda_runtime.h>
#include <cuda_fp16.h>
#include <math.h>

#define BSZ    256
#define PRIOR  60
#define FRAMES 240
#define POSE   768
#define PRED   180
#define CHUNK  10
#define EPSBN  1e-5f

__device__ float g_p1  [BSZ * PRED * POSE];
__device__ float g_p   [BSZ * PRED * POSE];
__device__ float g_xr  [BSZ * PRIOR * POSE];
__device__ float g_wr1 [3 * 192 * 64];
__device__ float g_wr2 [3 * 192 * 192];
__device__ float g_w1cat[2 * POSE * CHUNK * POSE];
__device__ float g_sw2 [POSE * POSE];
__device__ float g_tw2 [POSE * POSE];
__device__ float g_pw2 [POSE * POSE];
__device__ float g_pw1T[POSE * POSE];
__device__ float g_bc  [POSE];
__device__ float g_Wt  [CHUNK * CHUNK * POSE];
__device__ float g_bt  [CHUNK];
__device__ float g_hsp [BSZ * POSE];
__device__ float g_htm [BSZ * POSE];
__device__ float g_mem [BSZ * POSE];
__device__ float g_mem2[BSZ * POSE];
__device__ float g_penc[BSZ * CHUNK];
__device__ float g_Mmat[POSE * CHUNK];
__device__ float g_part[24 * 256 * 1536];
__device__ __half g_xf [BSZ * PRIOR * POSE];
__device__ __half g_pf [BSZ * PRED * POSE];
__device__ __half g_Wcf[POSE * POSE];

__device__ __forceinline__ float warp_sum(float v) {
    #pragma unroll
    for (int o = 16; o; o >>= 1) v += __shfl_xor_sync(0xffffffffu, v, o);
    return v;
}
__device__ __forceinline__ unsigned f2tf(float x) {
    unsigned u;
    asm("cvt.rna.tf32.f32 %0, %1;" : "=r"(u) : "f"(x));
    return u;
}
__device__ __forceinline__ float rnd(float x) { return __uint_as_float(f2tf(x)); }

__device__ __forceinline__ void cp16(unsigned d, const void* s, bool p) {
    asm volatile("cp.async.ca.shared.global [%0], [%1], 16, %2;"
                 :: "r"(d), "l"(s), "r"(p ? 16 : 0));
}
#define CP_COMMIT() asm volatile("cp.async.commit_group;" ::: "memory")
#define CP_WAIT1()  asm volatile("cp.async.wait_group 1;" ::: "memory")
#define CP_WAIT2()  asm volatile("cp.async.wait_group 2;" ::: "memory")

__device__ __forceinline__ unsigned s2u(const void* p) {
    unsigned a;
    asm("{ .reg .u64 t; cvta.to.shared.u64 t, %1; cvt.u32.u64 %0, t; }" : "=r"(a) : "l"(p));
    return a;
}
__device__ __forceinline__ void ldsm4(unsigned &r0, unsigned &r1, unsigned &r2, unsigned &r3,
                                      unsigned addr)
{
    asm volatile("ldmatrix.sync.aligned.m8n8.x4.shared.b16 {%0,%1,%2,%3}, [%4];"
                 : "=r"(r0), "=r"(r1), "=r"(r2), "=r"(r3) : "r"(addr));
}
#define MMA_TF32(acc, a, b0v, b1v) \
    asm volatile( \
        "mma.sync.aligned.m16n8k8.row.col.f32.tf32.tf32.f32 " \
        "{%0,%1,%2,%3},{%4,%5,%6,%7},{%8,%9},{%0,%1,%2,%3};" \
        : "+f"((acc)[0]), "+f"((acc)[1]), "+f"((acc)[2]), "+f"((acc)[3]) \
        : "r"((a)[0]), "r"((a)[1]), "r"((a)[2]), "r"((a)[3]), \
          "r"(b0v), "r"(b1v))
#define MMA_FP16(acc, a, b0v, b1v) \
    asm volatile( \
        "mma.sync.aligned.m16n8k16.row.col.f32.f16.f16.f32 " \
        "{%0,%1,%2,%3},{%4,%5,%6,%7},{%8,%9},{%0,%1,%2,%3};" \
        : "+f"((acc)[0]), "+f"((acc)[1]), "+f"((acc)[2]), "+f"((acc)[3]) \
        : "r"((a)[0]), "r"((a)[1]), "r"((a)[2]), "r"((a)[3]), \
          "r"(b0v), "r"(b1v))

template<int MT>
__device__ __forceinline__ void mma_slab(unsigned aA, unsigned aB, float acc[MT][4][4])
{
    #pragma unroll
    for (int ks = 0; ks < 16; ks += 8) {
        unsigned a[MT][4], b[2][4];
        #pragma unroll
        for (int mt = 0; mt < MT; mt++)
            ldsm4(a[mt][0], a[mt][1], a[mt][2], a[mt][3], aA + (mt * 16 * 20 + ks) * 4);
        #pragma unroll
        for (int np = 0; np < 2; np++)
            ldsm4(b[np][0], b[np][1], b[np][2], b[np][3], aB + (np * 16 * 20 + ks) * 4);
        #pragma unroll
        for (int mt = 0; mt < MT; mt++)
            #pragma unroll
            for (int nt = 0; nt < 4; nt++)
                MMA_TF32(acc[mt][nt], a[mt],
                         b[nt >> 1][(nt & 1) * 2], b[nt >> 1][(nt & 1) * 2 + 1]);
    }
}

// ---------------- generic tf32 GEMM (unchanged, known-good) ----------------
__global__ __launch_bounds__(256, 2)
void gemm_bt_ms(const float* __restrict__ A, long lda,
                const float* __restrict__ B, long ldb,
                float* __restrict__ Cpart,
                int M, int N, int K, int kchunk, int ldcN, int coffs)
{
    extern __shared__ unsigned sh[];
    unsigned shbase = s2u(sh);
    const unsigned STG = 128u * 20u * 4u;
    const unsigned bsoff = 4u * STG;
    const int tid = threadIdx.x;
    const int warpid = tid >> 5, lane = tid & 31;
    const int mbase = (warpid >> 2) * 64, nbase = (warpid & 3) * 32;
    const int quad = lane >> 3, qr = lane & 7;
    const int bm = blockIdx.y * 128, bn = blockIdx.x * 128;
    const int k0base = blockIdx.z * kchunk;
    const int kend = min(k0base + kchunk, K);
    const int nk = (kend - k0base) >> 4;
    const unsigned aAq = shbase + (((mbase + (quad & 1) * 8 + qr) * 20 + (quad >> 1) * 4) * 4);
    const unsigned aBq = shbase + bsoff + (((nbase + (quad >> 1) * 8 + qr) * 20 + (quad & 1) * 4) * 4);

    float acc[4][4][4];
    #pragma unroll
    for (int mt = 0; mt < 4; mt++)
        #pragma unroll
        for (int nt = 0; nt < 4; nt++)
            #pragma unroll
            for (int r = 0; r < 4; r++) acc[mt][nt][r] = 0.f;

    const int m_ = tid >> 2, kq = tid & 3;
    auto load = [&](int st, int k0) {
        #pragma unroll
        for (int i = 0; i < 2; i++) {
            int m = m_ + i * 64;
            int gk = k0 + kq * 4;
            cp16(shbase + st * STG + (m * 20 + kq * 4) * 4,
                 A + (long)(bm + m) * lda + gk, bm + m < M);
            cp16(shbase + bsoff + st * STG + (m * 20 + kq * 4) * 4,
                 B + (long)(bn + m) * ldb + gk, bn + m < N);
        }
    };
    #pragma unroll
    for (int s = 0; s < 3; s++) {
        if (s < nk) load(s, k0base + s * 16);
        CP_COMMIT();
    }
    for (int i = 0; i < nk; i++) {
        CP_WAIT2();
        __syncthreads();
        if (i + 3 < nk) load((i + 3) & 3, k0base + (i + 3) * 16);
        CP_COMMIT();
        int st = i & 3;
        mma_slab<4>(aAq + st * STG, aBq + st * STG, acc);
    }
    float* Cz = Cpart + (long)blockIdx.z * M * ldcN;
    #pragma unroll
    for (int mt = 0; mt < 4; mt++) {
        int gm0 = bm + mbase + mt * 16 + (lane >> 2);
        #pragma unroll
        for (int nt = 0; nt < 4; nt++) {
            int gn0 = bn + nbase + nt * 8 + (lane & 3) * 2;
            if (gm0 < M && gn0 < N) {
                Cz[(long)gm0 * ldcN + coffs + gn0]     = acc[mt][nt][0];
                Cz[(long)gm0 * ldcN + coffs + gn0 + 1] = acc[mt][nt][1];
            }
            if (gm0 + 8 < M && gn0 < N) {
                Cz[(long)(gm0 + 8) * ldcN + coffs + gn0]     = acc[mt][nt][2];
                Cz[(long)(gm0 + 8) * ldcN + coffs + gn0 + 1] = acc[mt][nt][3];
            }
        }
    }
}

// ---------------- tap-decomposed conv (R7-proven; + optional fp16 copy) ----
template<int ICH>
__global__ __launch_bounds__(256, 2)
void conv_tap(const float* __restrict__ X,
              const float* __restrict__ Wr,
              const float* __restrict__ cb,
              const float* __restrict__ bg, const float* __restrict__ bb,
              const float* __restrict__ bmn, const float* __restrict__ bv,
              float* __restrict__ Out, __half* __restrict__ Oh)
{
    constexpr int ICHP = (ICH + 63) & ~63;
    constexpr int NK = ICHP / 16;
    extern __shared__ unsigned sh[];
    unsigned shbase = s2u(sh);
    const unsigned ASTG = 288u * 20u * 4u;
    const unsigned BSTG = 16u * 136u * 4u;
    const unsigned bsoff = 3u * ASTG;
    const int b = blockIdx.z;
    const float* Xb = X + (long)b * ICH * POSE;
    const int tid = threadIdx.x;
    const int warpid = tid >> 5, lane = tid & 31;
    const int mbase = (warpid >> 2) * 48, nbase = (warpid & 3) * 32;
    const int quad = lane >> 3, qr = lane & 7;
    const int gid = lane >> 2, tig = lane & 3;
    const int bm = blockIdx.y * 96, bn = blockIdx.x * 128;
    const unsigned aAq = shbase + (((mbase + (quad & 1) * 8 + qr) * 20 + (quad >> 1) * 4) * 4);
    const int bBq = (int)(bsoff >> 2) + tig * 136 + 3 + nbase + gid;

    float acc[3][4][4];
    #pragma unroll
    for (int mt = 0; mt < 3; mt++)
        #pragma unroll
        for (int nt = 0; nt < 4; nt++)
            #pragma unroll
            for (int r = 0; r < 4; r++) acc[mt][nt][r] = 0.f;

    auto load = [&](int st, int k0) {
        #pragma unroll
        for (int i = 0; i < 5; i++) {
            int f = tid + i * 256;
            if (f < 1152) {
                int tap = f / 384, rem = f - tap * 384;
                int m = rem >> 2, kq = rem & 3;
                cp16(shbase + st * ASTG + ((tap * 96 + m) * 20 + kq * 4) * 4,
                     Wr + ((long)tap * 192 + bm + m) * ICHP + k0 + kq * 4, true);
            }
        }
        #pragma unroll
        for (int i = 0; i < 3; i++) {
            int f = tid + i * 256;
            if (f < 544) {
                int kk = f / 34, j = f - kk * 34;
                int pos0 = bn - 4 + j * 4;
                bool p = (k0 + kk < ICH) && (pos0 >= 0) && (pos0 < POSE);
                cp16(shbase + bsoff + st * BSTG + (kk * 136 + j * 4) * 4,
                     Xb + (long)(k0 + kk) * POSE + pos0, p);
            }
        }
    };
    #pragma unroll
    for (int s = 0; s < 2; s++) {
        if (s < NK) load(s, s * 16);
        CP_COMMIT();
    }
    const unsigned* shu = sh;
    for (int i = 0; i < NK; i++) {
        CP_WAIT1();
        __syncthreads();
        if (i + 2 < NK) load((i + 2) % 3, (i + 2) * 16);
        CP_COMMIT();
        int st = i % 3;
        unsigned aA = aAq + st * ASTG;
        int bB = bBq + st * (int)(BSTG >> 2);
        #pragma unroll
        for (int t = 0; t < 3; t++) {
            #pragma unroll
            for (int ks = 0; ks < 16; ks += 8) {
                unsigned a[3][4];
                #pragma unroll
                for (int mt = 0; mt < 3; mt++)
                    ldsm4(a[mt][0], a[mt][1], a[mt][2], a[mt][3],
                          aA + ((t * 96 + mt * 16) * 20 + ks) * 4);
                #pragma unroll
                for (int nt = 0; nt < 4; nt++) {
                    unsigned b0 = shu[bB + ks * 136 + t + nt * 8];
                    unsigned b1 = shu[bB + (ks + 4) * 136 + t + nt * 8];
                    #pragma unroll
                    for (int mt = 0; mt < 3; mt++)
                        MMA_TF32(acc[mt][nt], a[mt], b0, b1);
                }
            }
        }
    }
    #pragma unroll
    for (int mt = 0; mt < 3; mt++) {
        #pragma unroll
        for (int half = 0; half < 2; half++) {
            int gm = bm + mbase + mt * 16 + (lane >> 2) + half * 8;
            if (gm < PRED) {
                float s  = bg[gm] * rsqrtf(bv[gm] + EPSBN);
                float sht = bb[gm] - bmn[gm] * s;
                float cv = cb[gm];
                #pragma unroll
                for (int nt = 0; nt < 4; nt++) {
                    int gn0 = bn + nbase + nt * 8 + (lane & 3) * 2;
                    float y0 = fmaxf(acc[mt][nt][half * 2]     + cv, 0.f);
                    float y1 = fmaxf(acc[mt][nt][half * 2 + 1] + cv, 0.f);
                    float v0 = rnd(y0 * s + sht), v1 = rnd(y1 * s + sht);
                    long o = ((long)b * PRED + gm) * POSE + gn0;
                    Out[o] = v0; Out[o + 1] = v1;
                    if (Oh) *(__half2*)(Oh + o) = __halves2half2(__float2half_rn(v0),
                                                                 __float2half_rn(v1));
                }
            }
        }
    }
}

// ---------------- fp16 final GEMM: CTA 128x256, warp 64x64, K-slab 32 ------
__global__ __launch_bounds__(256)
void final_hp(const __half* __restrict__ xf, const __half* __restrict__ pf,
              const __half* __restrict__ Wf, const float* __restrict__ bias,
              float* __restrict__ C)
{
    extern __shared__ unsigned sh[];
    __shared__ const __half* rowp[128];
    unsigned shbase = s2u(sh);
    const unsigned ASTG = 128u * 40u * 2u;   // 10240 B
    const unsigned BSTG = 256u * 40u * 2u;   // 20480 B
    const unsigned bsoff = 4u * ASTG;

    const int tid = threadIdx.x;
    const int warpid = tid >> 5, lane = tid & 31;
    const int mbase = (warpid >> 2) * 64, nbase = (warpid & 3) * 64;
    const int quad = lane >> 3, qr = lane & 7;
    const int bm = blockIdx.y * 128, bn = blockIdx.x * 256;
    const int nk = POSE / 32;  // 24

    if (tid < 128) {
        int r = bm + tid;
        int bb_ = r / FRAMES, f = r - bb_ * FRAMES;
        rowp[tid] = (f < PRIOR) ? xf + ((long)bb_ * PRIOR + f) * POSE
                                : pf + ((long)bb_ * PRED + (f - PRIOR)) * POSE;
    }
    __syncthreads();

    // A frags: (m0-7,k0-7),(m8-15,k0-7),(m0-7,k8-15),(m8-15,k8-15)
    const unsigned aAq = shbase + (((mbase + (quad & 1) * 8 + qr) * 40 + (quad >> 1) * 8) * 2);
    // B frags: (n0-7,k0-7),(n0-7,k8-15),(n8-15,k0-7),(n8-15,k8-15)
    const unsigned aBq = shbase + bsoff + (((nbase + (quad >> 1) * 8 + qr) * 40 + (quad & 1) * 8) * 2);

    float acc[4][8][4];
    #pragma unroll
    for (int mt = 0; mt < 4; mt++)
        #pragma unroll
        for (int nt = 0; nt < 8; nt++)
            #pragma unroll
            for (int r = 0; r < 4; r++) acc[mt][nt][r] = 0.f;

    const int m_ = tid >> 2, kq = tid & 3;
    auto load = [&](int st, int k0) {
        int gk = k0 + kq * 8;   // 8 halves = 16B per cp
        #pragma unroll
        for (int i = 0; i < 2; i++) {
            int m = m_ + i * 64;
            cp16(shbase + st * ASTG + (m * 40 + kq * 8) * 2, rowp[m] + gk, true);
        }
        #pragma unroll
        for (int i = 0; i < 4; i++) {
            int n = m_ + i * 64;
            cp16(shbase + bsoff + st * BSTG + (n * 40 + kq * 8) * 2,
                 Wf + (long)(bn + n) * POSE + gk, true);
        }
    };

    #pragma unroll
    for (int s = 0; s < 3; s++) { load(s, s * 32); CP_COMMIT(); }
    for (int i = 0; i < nk; i++) {
        CP_WAIT2();
        __syncthreads();
        if (i + 3 < nk) load((i + 3) & 3, (i + 3) * 32);
        CP_COMMIT();
        int st = i & 3;
        unsigned aA = aAq + st * ASTG, aB = aBq + st * BSTG;
        #pragma unroll
        for (int kh = 0; kh < 2; kh++) {     // two k-16 halves of the 32-slab
            unsigned a[4][4], b[4][4];
            #pragma unroll
            for (int mt = 0; mt < 4; mt++)
                ldsm4(a[mt][0], a[mt][1], a[mt][2], a[mt][3],
                      aA + (mt * 16 * 40 + kh * 16) * 2);
            #pragma unroll
            for (int np = 0; np < 4; np++)
                ldsm4(b[np][0], b[np][1], b[np][2], b[np][3],
                      aB + (np * 16 * 40 + kh * 16) * 2);
            #pragma unroll
            for (int mt = 0; mt < 4; mt++)
                #pragma unroll
                for (int nt = 0; nt < 8; nt++)
                    MMA_FP16(acc[mt][nt], a[mt],
                             b[nt >> 1][(nt & 1) * 2], b[nt >> 1][(nt & 1) * 2 + 1]);
        }
    }

    #pragma unroll
    for (int mt = 0; mt < 4; mt++) {
        int gm0 = bm + mbase + mt * 16 + (lane >> 2);
        #pragma unroll
        for (int nt = 0; nt < 8; nt++) {
            int gn0 = bn + nbase + nt * 8 + (lane & 3) * 2;
            float2 bv = *(const float2*)(bias + gn0);
            float2 v0 = make_float2(acc[mt][nt][0] + bv.x, acc[mt][nt][1] + bv.y);
            float2 v1 = make_float2(acc[mt][nt][2] + bv.x, acc[mt][nt][3] + bv.y);
            *(float2*)(C + (long)gm0 * POSE + gn0)       = v0;
            *(float2*)(C + (long)(gm0 + 8) * POSE + gn0) = v1;
        }
    }
}

// ---------------- prep / glue ----------------
struct R8 { const float4* s[8]; float4* d[8]; int n4[8]; };
__global__ void k_round8(R8 r, int total4, __half* __restrict__ xf)
{
    int gid = blockIdx.x * blockDim.x + threadIdx.x;
    if (gid >= total4) return;
    #pragma unroll
    for (int k = 0; k < 8; k++) {
        if (gid < r.n4[k]) {
            float4 v = r.s[k][gid];
            float4 o = make_float4(rnd(v.x), rnd(v.y), rnd(v.z), rnd(v.w));
            r.d[k][gid] = o;
            if (k == 0) {
                ((__half2*)xf)[gid * 2]     = __halves2half2(__float2half_rn(o.x),
                                                             __float2half_rn(o.y));
                ((__half2*)xf)[gid * 2 + 1] = __halves2half2(__float2half_rn(o.z),
                                                             __float2half_rn(o.w));
            }
            return;
        }
        gid -= r.n4[k];
    }
}

__global__ void k_convw(const float* __restrict__ w1, const float* __restrict__ w2,
                        float* __restrict__ Wr1, float* __restrict__ Wr2)
{
    const int N1 = 3 * 192 * 64, N2 = 3 * 192 * 192;
    int t = blockIdx.x * blockDim.x + threadIdx.x;
    if (t < N1) {
        int tap = t / (192 * 64), rem = t % (192 * 64);
        int o = rem / 64, ich = rem % 64;
        float v = 0.f;
        if (o < PRED && ich < PRIOR) v = rnd(w1[(o * PRIOR + ich) * 3 + tap]);
        Wr1[t] = v;
    } else if (t < N1 + N2) {
        t -= N1;
        int tap = t / (192 * 192), rem = t % (192 * 192);
        int o = rem / 192, ich = rem % 192;
        float v = 0.f;
        if (o < PRED && ich < PRED) v = rnd(w2[(o * PRED + ich) * 3 + tap]);
        Wr2[t] = v;
    }
}

__global__ void k_trT(const float* __restrict__ s, float* __restrict__ d)
{
    __shared__ float t[32][33];
    int x0 = blockIdx.x * 32, y0 = blockIdx.y * 32;
    for (int i = threadIdx.y; i < 32; i += 8)
        t[i][threadIdx.x] = s[(long)(y0 + i) * POSE + x0 + threadIdx.x];
    __syncthreads();
    for (int i = threadIdx.y; i < 32; i += 8)
        d[(long)(x0 + i) * POSE + y0 + threadIdx.x] = rnd(t[threadIdx.x][i]);
}

__global__ void reduce2(const float* __restrict__ part, int S,
                        const float* __restrict__ ba, const float* __restrict__ bb,
                        float* __restrict__ oa, float* __restrict__ ob, int doRound)
{
    const int MN = BSZ * 1536;
    int i = blockIdx.x * blockDim.x + threadIdx.x;
    if (i >= MN) return;
    float s = 0.f;
    for (int z = 0; z < S; z++) s += part[(long)z * MN + i];
    int m = i / 1536, n = i - m * 1536;
    float* o; int nn;
    if (n < 768) { o = oa; nn = n; s += ba[n]; }
    else         { o = ob; nn = n - 768; s += bb[nn]; }
    o[m * 768 + nn] = doRound ? rnd(s) : s;
}

// Wc reduce: tf32 round, then fp16 for the final GEMM.
__global__ void reduce_wch(const float* __restrict__ part,
                           __half* __restrict__ Wf, int MN, int S)
{
    int i = blockIdx.x * blockDim.x + threadIdx.x;
    if (i >= MN) return;
    float s = 0.f;
    for (int z = 0; z < S; z++) s += part[(long)z * MN + i];
    Wf[i] = __float2half_rn(rnd(s));
}

__global__ void k_bc(const float* __restrict__ w2, const float* __restrict__ b1,
                     const float* __restrict__ b2, float* __restrict__ bc)
{
    int w = (blockIdx.x * blockDim.x + threadIdx.x) >> 5;
    int lane = threadIdx.x & 31;
    if (w >= POSE) return;
    float s = 0.f;
    for (int m = lane; m < POSE; m += 32) s += w2[(long)w * POSE + m] * b1[m];
    s = warp_sum(s);
    if (lane == 0) bc[w] = s + b2[w];
}

__global__ void k_tmm(const float* __restrict__ w1, const float* __restrict__ b1,
                      const float* __restrict__ w2, const float* __restrict__ b2,
                      float* __restrict__ Wt, float* __restrict__ bt)
{
    int idx = blockIdx.x * blockDim.x + threadIdx.x;
    const int KK = CHUNK * POSE;
    if (idx < CHUNK * KK) {
        int c = idx / KK, k = idx - c * KK;
        float s = 0.f;
        #pragma unroll
        for (int m = 0; m < CHUNK; m++) s += w2[c * CHUNK + m] * w1[(long)m * KK + k];
        Wt[idx] = s;
    }
    if (idx < CHUNK) {
        float s = b2[idx];
        #pragma unroll
        for (int m = 0; m < CHUNK; m++) s += w2[idx * CHUNK + m] * b1[m];
        bt[idx] = s;
    }
}

__global__ __launch_bounds__(320)
void gate_penc(float* __restrict__ p, const float* __restrict__ mem,
               const float* __restrict__ Wt, const float* __restrict__ bt,
               float* __restrict__ penc)
{
    __shared__ float sm[POSE];
    __shared__ float chunk[CHUNK * POSE];
    __shared__ float sig[CHUNK];
    const int b = blockIdx.x, t = threadIdx.x;
    float* pb = p + (long)b * PRED * POSE;
    for (int i = t; i < POSE; i += 320) sm[i] = mem[(long)b * POSE + i];
    for (int i = t; i < CHUNK * POSE; i += 320) chunk[i] = pb[i];
    __syncthreads();
    const int w = t >> 5, lane = t & 31;
    float s = 0.f;
    for (int d = lane; d < POSE; d += 32) s += sm[d] * chunk[w * POSE + d];
    s = warp_sum(s);
    if (lane == 0) sig[w] = 1.f / (1.f + expf(-s));
    __syncthreads();
    for (int i = t; i < CHUNK * POSE; i += 320) {
        int c = i / POSE, d = i - c * POSE;
        float g = sig[c];
        chunk[i] = g * chunk[i] + (1.f - g) * sm[d];
    }
    __syncthreads();
    for (int i = t; i < CHUNK * POSE; i += 320) pb[i] = rnd(chunk[i]);
    float acc = 0.f;
    for (int k = lane; k < CHUNK * POSE; k += 32) acc += chunk[k] * Wt[(long)w * CHUNK * POSE + k];
    acc = warp_sum(acc);
    if (lane == 0) penc[b * CHUNK + w] = acc + bt[w];
}

__global__ void k_M(const float* __restrict__ mem2, const float* __restrict__ penc,
                    float* __restrict__ Mo)
{
    __shared__ float pe[BSZ * CHUNK];
    const int t = threadIdx.x;
    for (int i = t; i < BSZ * CHUNK; i += 256) pe[i] = penc[i];
    __syncthreads();
    int d = blockIdx.x * 256 + t;
    float acc[CHUNK];
    #pragma unroll
    for (int c = 0; c < CHUNK; c++) acc[c] = 0.f;
    for (int b = 0; b < BSZ; b++) {
        float mv = mem2[(long)b * POSE + d];
        #pragma unroll
        for (int c = 0; c < CHUNK; c++) acc[c] = fmaf(mv, pe[b * CHUNK + c], acc[c]);
    }
    #pragma unroll
    for (int c = 0; c < CHUNK; c++) Mo[d * CHUNK + c] = acc[c];
}

// score2 + final p update; also re-emits fp16 chunk rows.
__global__ __launch_bounds__(320)
void k_score2(float* __restrict__ p, const float* __restrict__ mem2,
              const float* __restrict__ Mo, __half* __restrict__ pf)
{
    __shared__ float sm[POSE];
    __shared__ float sc[CHUNK];
    __shared__ float softs[CHUNK];
    const int b = blockIdx.x, t = threadIdx.x;
    for (int i = t; i < POSE; i += 320) sm[i] = mem2[(long)b * POSE + i];
    __syncthreads();
    const int w = t >> 5, lane = t & 31;
    float s = 0.f;
    for (int d = lane; d < POSE; d += 32) s += sm[d] * Mo[d * CHUNK + w];
    s = warp_sum(s);
    if (lane == 0) sc[w] = s;
    __syncthreads();
    if (t == 0) {
        float mx = sc[0];
        #pragma unroll
        for (int c = 1; c < CHUNK; c++) mx = fmaxf(mx, sc[c]);
        float ssum = 0.f;
        #pragma unroll
        for (int c = 0; c < CHUNK; c++) { float e = expf(sc[c] - mx); softs[c] = e; ssum += e; }
        float inv = 1.f / ssum;
        #pragma unroll
        for (int c = 0; c < CHUNK; c++) softs[c] *= inv;
    }
    __syncthreads();
    float* pb = p + (long)b * PRED * POSE;
    __half* pfb = pf + (long)b * PRED * POSE;
    for (int i = t; i < CHUNK * POSE; i += 320) {
        int c = i / POSE;
        float v = rnd(pb[i] * (1.f + softs[c]));
        pb[i] = v;
        pfb[i] = __float2half_rn(v);
    }
}

// ---------------- launch ----------------
extern "C" void kernel_launch(void* const* d_in, const int* in_sizes, int n_in,
                              void* d_out, int out_size)
{
    const float* x       = (const float*)d_in[0];
    const float* conv1_w = (const float*)d_in[1];
    const float* conv1_b = (const float*)d_in[2];
    const float* bn1_g   = (const float*)d_in[3];
    const float* bn1_b   = (const float*)d_in[4];
    const float* bn1_m   = (const float*)d_in[5];
    const float* bn1_v   = (const float*)d_in[6];
    const float* conv2_w = (const float*)d_in[7];
    const float* conv2_b = (const float*)d_in[8];
    const float* bn2_g   = (const float*)d_in[9];
    const float* bn2_b   = (const float*)d_in[10];
    const float* bn2_m   = (const float*)d_in[11];
    const float* bn2_v   = (const float*)d_in[12];
    const float* sp_w1   = (const float*)d_in[13];
    const float* sp_b1   = (const float*)d_in[14];
    const float* sp_w2   = (const float*)d_in[15];
    const float* sp_b2   = (const float*)d_in[16];
    const float* tmc_w1  = (const float*)d_in[17];
    const float* tmc_b1  = (const float*)d_in[18];
    const float* tmc_w2  = (const float*)d_in[19];
    const float* tmc_b2  = (const float*)d_in[20];
    const float* tmm_w1  = (const float*)d_in[21];
    const float* tmm_b1  = (const float*)d_in[22];
    const float* tmm_w2  = (const float*)d_in[23];
    const float* tmm_b2  = (const float*)d_in[24];
    const float* post_w1 = (const float*)d_in[25];
    const float* post_b1 = (const float*)d_in[26];
    const float* post_w2 = (const float*)d_in[27];
    const float* post_b2 = (const float*)d_in[28];

    float *p1, *p, *xr, *wr1, *wr2, *w1cat, *sw2, *tw2, *pw2, *pw1T;
    float *bc, *Wt, *bt, *hsp, *htm, *mem, *mem2, *penc, *Mm, *part;
    __half *xf, *pf, *Wcf;
    cudaGetSymbolAddress((void**)&p1,    g_p1);
    cudaGetSymbolAddress((void**)&p,     g_p);
    cudaGetSymbolAddress((void**)&xr,    g_xr);
    cudaGetSymbolAddress((void**)&wr1,   g_wr1);
    cudaGetSymbolAddress((void**)&wr2,   g_wr2);
    cudaGetSymbolAddress((void**)&w1cat, g_w1cat);
    cudaGetSymbolAddress((void**)&sw2,   g_sw2);
    cudaGetSymbolAddress((void**)&tw2,   g_tw2);
    cudaGetSymbolAddress((void**)&pw2,   g_pw2);
    cudaGetSymbolAddress((void**)&pw1T,  g_pw1T);
    cudaGetSymbolAddress((void**)&bc,    g_bc);
    cudaGetSymbolAddress((void**)&Wt,    g_Wt);
    cudaGetSymbolAddress((void**)&bt,    g_bt);
    cudaGetSymbolAddress((void**)&hsp,   g_hsp);
    cudaGetSymbolAddress((void**)&htm,   g_htm);
    cudaGetSymbolAddress((void**)&mem,   g_mem);
    cudaGetSymbolAddress((void**)&mem2,  g_mem2);
    cudaGetSymbolAddress((void**)&penc,  g_penc);
    cudaGetSymbolAddress((void**)&Mm,    g_Mmat);
    cudaGetSymbolAddress((void**)&part,  g_part);
    cudaGetSymbolAddress((void**)&xf,    g_xf);
    cudaGetSymbolAddress((void**)&pf,    g_pf);
    cudaGetSymbolAddress((void**)&Wcf,   g_Wcf);

    const int SMEM_GEMM  = 4 * 128 * 20 * 4 * 2;
    const int SMEM_CONV  = 3 * (288 * 20 + 16 * 136) * 4;
    const int SMEM_HP    = 4 * (128 * 40 + 256 * 40) * 2;    // 122880
    cudaFuncSetAttribute(gemm_bt_ms,    cudaFuncAttributeMaxDynamicSharedMemorySize, SMEM_GEMM);
    cudaFuncSetAttribute(final_hp,      cudaFuncAttributeMaxDynamicSharedMemorySize, SMEM_HP);
    cudaFuncSetAttribute(conv_tap<60>,  cudaFuncAttributeMaxDynamicSharedMemorySize, SMEM_CONV);
    cudaFuncSetAttribute(conv_tap<180>, cudaFuncAttributeMaxDynamicSharedMemorySize, SMEM_CONV);

    R8 r;
    const float* srcs[8] = { x, sp_w1, tmc_w1, sp_w2, tmc_w2, post_w2, x, x };
    float* dsts[8]       = { xr, w1cat, w1cat + POSE * CHUNK * POSE, sw2, tw2, pw2, xr, xr };
    int ns[8] = { BSZ*PRIOR*POSE, POSE*CHUNK*POSE, POSE*CHUNK*POSE,
                  POSE*POSE, POSE*POSE, POSE*POSE, 0, 0 };
    int total4 = 0;
    for (int i = 0; i < 8; i++) {
        r.s[i] = (const float4*)srcs[i]; r.d[i] = (float4*)dsts[i];
        r.n4[i] = ns[i] / 4; total4 += ns[i] / 4;
    }
    k_round8<<<(total4 + 255) / 256, 256>>>(r, total4, xf);
    k_convw<<<(3*192*64 + 3*192*192 + 255) / 256, 256>>>(conv1_w, conv2_w, wr1, wr2);

    // 2: conv1   3: conv2 (ncu capture = launch index 3; conv2 also emits fp16 p)
    conv_tap<60><<<dim3(6, 2, BSZ), 256, SMEM_CONV>>>(xr, wr1, conv1_b,
                                                      bn1_g, bn1_b, bn1_m, bn1_v, p1, nullptr);
    conv_tap<180><<<dim3(6, 2, BSZ), 256, SMEM_CONV>>>(p1, wr2, conv2_b,
                                                       bn2_g, bn2_b, bn2_m, bn2_v, p, pf);

    k_trT<<<dim3(24, 24), dim3(32, 8)>>>(post_w1, pw1T);
    k_bc<<<96, 256>>>(post_w2, post_b1, post_b2, bc);
    k_tmm<<<300, 256>>>(tmm_w1, tmm_b1, tmm_w2, tmm_b2, Wt, bt);

    const float* tail = xr + (PRIOR - CHUNK) * POSE;
    gemm_bt_ms<<<dim3(12, 2, 16), 256, SMEM_GEMM>>>(tail, (long)PRIOR * POSE, w1cat,
        (long)CHUNK * POSE, part, BSZ, 2 * POSE, CHUNK * POSE, 480, 1536, 0);
    reduce2<<<(BSZ * 1536 + 255) / 256, 256>>>(part, 16, sp_b1, tmc_b1, hsp, htm, 1);
    gemm_bt_ms<<<dim3(6, 2, 8), 256, SMEM_GEMM>>>(hsp, POSE, sw2, POSE,
        part, BSZ, POSE, POSE, 96, 1536, 0);
    gemm_bt_ms<<<dim3(6, 2, 8), 256, SMEM_GEMM>>>(htm, POSE, tw2, POSE,
        part, BSZ, POSE, POSE, 96, 1536, 768);
    reduce2<<<(BSZ * 1536 + 255) / 256, 256>>>(part, 8, sp_b2, tmc_b2, mem, mem2, 0);

    gemm_bt_ms<<<dim3(6, 6, 8), 256, SMEM_GEMM>>>(pw2, POSE, pw1T, POSE,
        part, POSE, POSE, POSE, 96, POSE, 0);
    reduce_wch<<<(POSE * POSE + 255) / 256, 256>>>(part, Wcf, POSE * POSE, 8);

    gate_penc<<<BSZ, 320>>>(p, mem, Wt, bt, penc);
    k_M<<<3, 256>>>(mem2, penc, Mm);
    k_score2<<<BSZ, 320>>>(p, mem2, Mm, pf);

    // fp16 tensor-core final GEMM -> d_out
    final_hp<<<dim3(3, 480), 256, SMEM_HP>>>(xf, pf, Wcf, bc, (float*)d_out);
}

// round 13
// speedup vs baseline: 1.2827x; 1.0735x over previous
#include <cuda_runtime.h>
#include <cuda_fp16.h>
#include <math.h>

#define BSZ    256
#define PRIOR  60
#define FRAMES 240
#define POSE   768
#define PRED   180
#define CHUNK  10
#define EPSBN  1e-5f

__device__ float  g_p   [BSZ * PRED * POSE];
__device__ __half g_p1T [BSZ * POSE * 192];     // conv1 out, transposed [b][pos][ich]
__device__ __half g_xT  [BSZ * POSE * 64];      // x transposed  [b][pos][ich]
__device__ __half g_wr1 [3 * 192 * 64];
__device__ __half g_wr2 [3 * 192 * 192];
__device__ __half g_w1cat[2 * POSE * CHUNK * POSE];
__device__ __half g_sw2 [POSE * POSE];
__device__ __half g_tw2 [POSE * POSE];
__device__ __half g_pw2 [POSE * POSE];
__device__ __half g_pw1T[POSE * POSE];
__device__ float  g_bc  [POSE];
__device__ float  g_Wt  [CHUNK * CHUNK * POSE];
__device__ float  g_bt  [CHUNK];
__device__ __half g_hsp [BSZ * POSE];
__device__ __half g_htm [BSZ * POSE];
__device__ float  g_mem [BSZ * POSE];
__device__ float  g_mem2[BSZ * POSE];
__device__ float  g_penc[BSZ * CHUNK];
__device__ float  g_Mmat[POSE * CHUNK];
__device__ float  g_part[16 * 256 * 1536];
__device__ __half g_xf [BSZ * PRIOR * POSE];
__device__ __half g_pf [BSZ * PRED * POSE];
__device__ __half g_Wcf[POSE * POSE];

__device__ __forceinline__ float warp_sum(float v) {
    #pragma unroll
    for (int o = 16; o; o >>= 1) v += __shfl_xor_sync(0xffffffffu, v, o);
    return v;
}
__device__ __forceinline__ unsigned f2tf(float x) {
    unsigned u;
    asm("cvt.rna.tf32.f32 %0, %1;" : "=r"(u) : "f"(x));
    return u;
}
__device__ __forceinline__ float rnd(float x) { return __uint_as_float(f2tf(x)); }

__device__ __forceinline__ void cp16(unsigned d, const void* s, bool p) {
    asm volatile("cp.async.ca.shared.global [%0], [%1], 16, %2;"
                 :: "r"(d), "l"(s), "r"(p ? 16 : 0));
}
#define CP_COMMIT() asm volatile("cp.async.commit_group;" ::: "memory")
#define CP_WAIT1()  asm volatile("cp.async.wait_group 1;" ::: "memory")
#define CP_WAIT2()  asm volatile("cp.async.wait_group 2;" ::: "memory")

__device__ __forceinline__ unsigned s2u(const void* p) {
    unsigned a;
    asm("{ .reg .u64 t; cvta.to.shared.u64 t, %1; cvt.u32.u64 %0, t; }" : "=r"(a) : "l"(p));
    return a;
}
__device__ __forceinline__ void ldsm4(unsigned &r0, unsigned &r1, unsigned &r2, unsigned &r3,
                                      unsigned addr)
{
    asm volatile("ldmatrix.sync.aligned.m8n8.x4.shared.b16 {%0,%1,%2,%3}, [%4];"
                 : "=r"(r0), "=r"(r1), "=r"(r2), "=r"(r3) : "r"(addr));
}
#define MMA_FP16(acc, a, b0v, b1v) \
    asm volatile( \
        "mma.sync.aligned.m16n8k16.row.col.f32.f16.f16.f32 " \
        "{%0,%1,%2,%3},{%4,%5,%6,%7},{%8,%9},{%0,%1,%2,%3};" \
        : "+f"((acc)[0]), "+f"((acc)[1]), "+f"((acc)[2]), "+f"((acc)[3]) \
        : "r"((a)[0]), "r"((a)[1]), "r"((a)[2]), "r"((a)[3]), \
          "r"(b0v), "r"(b1v))

// ---------------------------------------------------------------------------
// Generic fp16 GEMM: A [M,K], B [N,K] (both k-contiguous halves), split-K
// fp32 partials. 128x128 CTA tile, warp 64x32, K-slab 32, 4-stage, 2 CTAs/SM.
// Fragment scheme identical to the R11-proven final_hp.
// ---------------------------------------------------------------------------
__global__ __launch_bounds__(256, 2)
void ghemm(const __half* __restrict__ A, long lda,
           const __half* __restrict__ B, long ldb,
           float* __restrict__ Cpart,
           int M, int N, int K, int kchunk, int ldcN, int coffs)
{
    extern __shared__ unsigned sh[];
    unsigned shbase = s2u(sh);
    const unsigned STG = 128u * 40u * 2u;   // 10240 B
    const unsigned bsoff = 4u * STG;

    const int tid = threadIdx.x;
    const int warpid = tid >> 5, lane = tid & 31;
    const int mbase = (warpid >> 2) * 64, nbase = (warpid & 3) * 32;
    const int quad = lane >> 3, qr = lane & 7;
    const int bm = blockIdx.y * 128, bn = blockIdx.x * 128;
    const int k0base = blockIdx.z * kchunk;
    const int nk = kchunk >> 5;

    const unsigned aAq = shbase + (((mbase + (quad & 1) * 8 + qr) * 40 + (quad >> 1) * 8) * 2);
    const unsigned aBq = shbase + bsoff + (((nbase + (quad >> 1) * 8 + qr) * 40 + (quad & 1) * 8) * 2);

    float acc[4][4][4];
    #pragma unroll
    for (int mt = 0; mt < 4; mt++)
        #pragma unroll
        for (int nt = 0; nt < 4; nt++)
            #pragma unroll
            for (int r = 0; r < 4; r++) acc[mt][nt][r] = 0.f;

    auto load = [&](int st, int k0) {
        #pragma unroll
        for (int i = 0; i < 2; i++) {
            int idx = tid + i * 256, r = idx >> 2, kq = idx & 3;
            cp16(shbase + st * STG + (r * 40 + kq * 8) * 2,
                 A + (long)(bm + r) * lda + k0 + kq * 8, bm + r < M);
            cp16(shbase + bsoff + st * STG + (r * 40 + kq * 8) * 2,
                 B + (long)(bn + r) * ldb + k0 + kq * 8, bn + r < N);
        }
    };
    #pragma unroll
    for (int s = 0; s < 3; s++) {
        if (s < nk) load(s, k0base + s * 32);
        CP_COMMIT();
    }
    for (int i = 0; i < nk; i++) {
        CP_WAIT2();
        __syncthreads();
        if (i + 3 < nk) load((i + 3) & 3, k0base + (i + 3) * 32);
        CP_COMMIT();
        int st = i & 3;
        unsigned aA = aAq + st * STG, aB = aBq + st * STG;
        #pragma unroll
        for (int kh = 0; kh < 2; kh++) {
            unsigned a[4][4], b[2][4];
            #pragma unroll
            for (int mt = 0; mt < 4; mt++)
                ldsm4(a[mt][0], a[mt][1], a[mt][2], a[mt][3],
                      aA + (mt * 16 * 40 + kh * 16) * 2);
            #pragma unroll
            for (int np = 0; np < 2; np++)
                ldsm4(b[np][0], b[np][1], b[np][2], b[np][3],
                      aB + (np * 16 * 40 + kh * 16) * 2);
            #pragma unroll
            for (int mt = 0; mt < 4; mt++)
                #pragma unroll
                for (int nt = 0; nt < 4; nt++)
                    MMA_FP16(acc[mt][nt], a[mt],
                             b[nt >> 1][(nt & 1) * 2], b[nt >> 1][(nt & 1) * 2 + 1]);
        }
    }
    float* Cz = Cpart + (long)blockIdx.z * M * ldcN;
    #pragma unroll
    for (int mt = 0; mt < 4; mt++) {
        int gm0 = bm + mbase + mt * 16 + (lane >> 2);
        #pragma unroll
        for (int nt = 0; nt < 4; nt++) {
            int gn0 = bn + nbase + nt * 8 + (lane & 3) * 2;
            if (gm0 < M && gn0 < N) {
                Cz[(long)gm0 * ldcN + coffs + gn0]     = acc[mt][nt][0];
                Cz[(long)gm0 * ldcN + coffs + gn0 + 1] = acc[mt][nt][1];
            }
            if (gm0 + 8 < M && gn0 < N) {
                Cz[(long)(gm0 + 8) * ldcN + coffs + gn0]     = acc[mt][nt][2];
                Cz[(long)(gm0 + 8) * ldcN + coffs + gn0 + 1] = acc[mt][nt][3];
            }
        }
    }
}

// ---------------------------------------------------------------------------
// fp16 tap-decomposed Conv1d(k=3,p=1). Input X k-major: [b][pos][ICHP] halves.
// B tile [pos][k] (rows of 16 halves, pitch 24): taps shift ROW index.
// A = Wr [3][192][ICHP] fp16 zero-padded. CTA 96x128, 3-stage, 2 CTAs/SM.
// Epilogues: OutT (transposed fp16, conv1) or OutF+OutH (conv2).
// ---------------------------------------------------------------------------
template<int ICH>
__global__ __launch_bounds__(256, 2)
void conv_hp(const __half* __restrict__ X,
             const __half* __restrict__ Wr,
             const float* __restrict__ cb,
             const float* __restrict__ bg, const float* __restrict__ bb,
             const float* __restrict__ bmn, const float* __restrict__ bv,
             float* __restrict__ OutF, __half* __restrict__ OutH,
             __half* __restrict__ OutT)
{
    constexpr int ICHP = (ICH + 63) & ~63;
    constexpr int NK = ICHP / 16;
    extern __shared__ unsigned sh[];
    unsigned shbase = s2u(sh);
    const unsigned ASTG = 288u * 24u * 2u;   // 13824 B
    const unsigned BSTG = 136u * 24u * 2u;   // 6528 B
    const unsigned bsoff = 3u * ASTG;

    const int b = blockIdx.z;
    const __half* Xb = X + (long)b * POSE * ICHP;
    const int tid = threadIdx.x;
    const int warpid = tid >> 5, lane = tid & 31;
    const int mbase = (warpid >> 2) * 48, nbase = (warpid & 3) * 32;
    const int quad = lane >> 3, qr = lane & 7;
    const int gid = lane >> 2, tig = lane & 3;
    const int bm = blockIdx.y * 96, bn = blockIdx.x * 128;

    const unsigned aAq = shbase + (((mbase + (quad & 1) * 8 + qr) * 24 + (quad >> 1) * 8) * 2);
    const int bW0 = (int)(bsoff >> 2);       // B region word base

    float acc[3][4][4];
    #pragma unroll
    for (int mt = 0; mt < 3; mt++)
        #pragma unroll
        for (int nt = 0; nt < 4; nt++)
            #pragma unroll
            for (int r = 0; r < 4; r++) acc[mt][nt][r] = 0.f;

    auto load = [&](int st, int k0) {
        #pragma unroll
        for (int i = 0; i < 3; i++) {
            int idx = tid + i * 256;
            if (idx < 576) {
                int tap = idx / 192, rem = idx - tap * 192;
                int m = rem >> 1, j = rem & 1;
                cp16(shbase + st * ASTG + ((tap * 96 + m) * 24 + j * 8) * 2,
                     Wr + ((long)tap * 192 + bm + m) * ICHP + k0 + j * 8, true);
            }
        }
        #pragma unroll
        for (int i = 0; i < 2; i++) {
            int idx = tid + i * 256;
            if (idx < 272) {
                int r = idx >> 1, j = idx & 1;
                int pos = bn - 4 + r;
                bool p = (pos >= 0) && (pos < POSE);
                cp16(shbase + bsoff + st * BSTG + (r * 24 + j * 8) * 2,
                     Xb + (long)(p ? pos : 0) * ICHP + k0 + j * 8, p);
            }
        }
    };
    #pragma unroll
    for (int s = 0; s < 2; s++) {
        if (s < NK) load(s, s * 16);
        CP_COMMIT();
    }
    const unsigned* shu = sh;
    for (int i = 0; i < NK; i++) {
        CP_WAIT1();
        __syncthreads();
        if (i + 2 < NK) load((i + 2) % 3, (i + 2) * 16);
        CP_COMMIT();
        int st = i % 3;
        unsigned aA = aAq + st * ASTG;
        int bW = bW0 + st * (int)(BSTG >> 2);
        #pragma unroll
        for (int t = 0; t < 3; t++) {
            unsigned a[3][4];
            #pragma unroll
            for (int mt = 0; mt < 3; mt++)
                ldsm4(a[mt][0], a[mt][1], a[mt][2], a[mt][3],
                      aA + ((t * 96 + mt * 16) * 24) * 2);
            #pragma unroll
            for (int nt = 0; nt < 4; nt++) {
                int row = nbase + nt * 8 + gid + t + 3;
                unsigned b0 = shu[bW + row * 12 + tig];
                unsigned b1 = shu[bW + row * 12 + tig + 4];
                #pragma unroll
                for (int mt = 0; mt < 3; mt++)
                    MMA_FP16(acc[mt][nt], a[mt], b0, b1);
            }
        }
    }

    #pragma unroll
    for (int mt = 0; mt < 3; mt++) {
        #pragma unroll
        for (int half_ = 0; half_ < 2; half_++) {
            int gm = bm + mbase + mt * 16 + (lane >> 2) + half_ * 8;
            if (gm < PRED) {
                float s  = bg[gm] * rsqrtf(bv[gm] + EPSBN);
                float sht = bb[gm] - bmn[gm] * s;
                float cv = cb[gm];
                #pragma unroll
                for (int nt = 0; nt < 4; nt++) {
                    int gn0 = bn + nbase + nt * 8 + (lane & 3) * 2;
                    float y0 = fmaxf(acc[mt][nt][half_ * 2]     + cv, 0.f);
                    float y1 = fmaxf(acc[mt][nt][half_ * 2 + 1] + cv, 0.f);
                    float v0 = rnd(y0 * s + sht), v1 = rnd(y1 * s + sht);
                    if (OutT) {
                        OutT[((long)b * POSE + gn0)     * 192 + gm] = __float2half_rn(v0);
                        OutT[((long)b * POSE + gn0 + 1) * 192 + gm] = __float2half_rn(v1);
                    } else {
                        long o = ((long)b * PRED + gm) * POSE + gn0;
                        OutF[o] = v0; OutF[o + 1] = v1;
                        *(__half2*)(OutH + o) = __halves2half2(__float2half_rn(v0),
                                                               __float2half_rn(v1));
                    }
                }
            }
        }
    }
}

// ---------------------------------------------------------------------------
// fp16 final GEMM (R11-proven): CTA 128x256, warp 64x64, K-slab 32, 4-stage.
// ---------------------------------------------------------------------------
__global__ __launch_bounds__(256)
void final_hp(const __half* __restrict__ xf, const __half* __restrict__ pf,
              const __half* __restrict__ Wf, const float* __restrict__ bias,
              float* __restrict__ C)
{
    extern __shared__ unsigned sh[];
    __shared__ const __half* rowp[128];
    unsigned shbase = s2u(sh);
    const unsigned ASTG = 128u * 40u * 2u;
    const unsigned BSTG = 256u * 40u * 2u;
    const unsigned bsoff = 4u * ASTG;

    const int tid = threadIdx.x;
    const int warpid = tid >> 5, lane = tid & 31;
    const int mbase = (warpid >> 2) * 64, nbase = (warpid & 3) * 64;
    const int quad = lane >> 3, qr = lane & 7;
    const int bm = blockIdx.y * 128, bn = blockIdx.x * 256;
    const int nk = POSE / 32;

    if (tid < 128) {
        int r = bm + tid;
        int bb_ = r / FRAMES, f = r - bb_ * FRAMES;
        rowp[tid] = (f < PRIOR) ? xf + ((long)bb_ * PRIOR + f) * POSE
                                : pf + ((long)bb_ * PRED + (f - PRIOR)) * POSE;
    }
    __syncthreads();

    const unsigned aAq = shbase + (((mbase + (quad & 1) * 8 + qr) * 40 + (quad >> 1) * 8) * 2);
    const unsigned aBq = shbase + bsoff + (((nbase + (quad >> 1) * 8 + qr) * 40 + (quad & 1) * 8) * 2);

    float acc[4][8][4];
    #pragma unroll
    for (int mt = 0; mt < 4; mt++)
        #pragma unroll
        for (int nt = 0; nt < 8; nt++)
            #pragma unroll
            for (int r = 0; r < 4; r++) acc[mt][nt][r] = 0.f;

    const int m_ = tid >> 2, kq = tid & 3;
    auto load = [&](int st, int k0) {
        int gk = k0 + kq * 8;
        #pragma unroll
        for (int i = 0; i < 2; i++) {
            int m = m_ + i * 64;
            cp16(shbase + st * ASTG + (m * 40 + kq * 8) * 2, rowp[m] + gk, true);
        }
        #pragma unroll
        for (int i = 0; i < 4; i++) {
            int n = m_ + i * 64;
            cp16(shbase + bsoff + st * BSTG + (n * 40 + kq * 8) * 2,
                 Wf + (long)(bn + n) * POSE + gk, true);
        }
    };

    #pragma unroll
    for (int s = 0; s < 3; s++) { load(s, s * 32); CP_COMMIT(); }
    for (int i = 0; i < nk; i++) {
        CP_WAIT2();
        __syncthreads();
        if (i + 3 < nk) load((i + 3) & 3, (i + 3) * 32);
        CP_COMMIT();
        int st = i & 3;
        unsigned aA = aAq + st * ASTG, aB = aBq + st * BSTG;
        #pragma unroll
        for (int kh = 0; kh < 2; kh++) {
            unsigned a[4][4], b[4][4];
            #pragma unroll
            for (int mt = 0; mt < 4; mt++)
                ldsm4(a[mt][0], a[mt][1], a[mt][2], a[mt][3],
                      aA + (mt * 16 * 40 + kh * 16) * 2);
            #pragma unroll
            for (int np = 0; np < 4; np++)
                ldsm4(b[np][0], b[np][1], b[np][2], b[np][3],
                      aB + (np * 16 * 40 + kh * 16) * 2);
            #pragma unroll
            for (int mt = 0; mt < 4; mt++)
                #pragma unroll
                for (int nt = 0; nt < 8; nt++)
                    MMA_FP16(acc[mt][nt], a[mt],
                             b[nt >> 1][(nt & 1) * 2], b[nt >> 1][(nt & 1) * 2 + 1]);
        }
    }

    #pragma unroll
    for (int mt = 0; mt < 4; mt++) {
        int gm0 = bm + mbase + mt * 16 + (lane >> 2);
        #pragma unroll
        for (int nt = 0; nt < 8; nt++) {
            int gn0 = bn + nbase + nt * 8 + (lane & 3) * 2;
            float2 bv = *(const float2*)(bias + gn0);
            float2 v0 = make_float2(acc[mt][nt][0] + bv.x, acc[mt][nt][1] + bv.y);
            float2 v1 = make_float2(acc[mt][nt][2] + bv.x, acc[mt][nt][3] + bv.y);
            *(float2*)(C + (long)gm0 * POSE + gn0)       = v0;
            *(float2*)(C + (long)(gm0 + 8) * POSE + gn0) = v1;
        }
    }
}

// ---------------- prep / glue ----------------
struct R6 { const float4* s[6]; __half2* d[6]; int n4[6]; };
__global__ void k_round_h(R6 r, int total4)
{
    int gid = blockIdx.x * blockDim.x + threadIdx.x;
    if (gid >= total4) return;
    #pragma unroll
    for (int k = 0; k < 6; k++) {
        if (gid < r.n4[k]) {
            float4 v = r.s[k][gid];
            r.d[k][gid * 2]     = __halves2half2(__float2half_rn(rnd(v.x)),
                                                 __float2half_rn(rnd(v.y)));
            r.d[k][gid * 2 + 1] = __halves2half2(__float2half_rn(rnd(v.z)),
                                                 __float2half_rn(rnd(v.w)));
            return;
        }
        gid -= r.n4[k];
    }
}

// x [b][60][768] -> xT fp16 [b][768][64]; also zero p1T pad cols 180-191.
__global__ void k_trx(const float* __restrict__ x, __half* __restrict__ xT,
                      __half* __restrict__ p1T)
{
    __shared__ float t[64][33];
    int b = blockIdx.y, pos0 = blockIdx.x * 32;
    int tx = threadIdx.x, ty = threadIdx.y;
    for (int ich = ty; ich < 64; ich += 8)
        t[ich][tx] = (ich < PRIOR) ? rnd(x[((long)b * PRIOR + ich) * POSE + pos0 + tx]) : 0.f;
    __syncthreads();
    int tid = ty * 32 + tx;
    for (int e = tid; e < 32 * 64; e += 256) {
        int r = e >> 6, ich = e & 63;
        xT[((long)b * POSE + pos0 + r) * 64 + ich] = __float2half_rn(t[ich][r]);
    }
    for (int e = tid; e < 32 * 12; e += 256) {
        int r = e / 12, j = e - r * 12;
        p1T[((long)b * POSE + pos0 + r) * 192 + 180 + j] = __float2half_rn(0.f);
    }
}

__global__ void k_convw(const float* __restrict__ w1, const float* __restrict__ w2,
                        __half* __restrict__ Wr1, __half* __restrict__ Wr2)
{
    const int N1 = 3 * 192 * 64, N2 = 3 * 192 * 192;
    int t = blockIdx.x * blockDim.x + threadIdx.x;
    if (t < N1) {
        int tap = t / (192 * 64), rem = t % (192 * 64);
        int o = rem / 64, ich = rem % 64;
        float v = 0.f;
        if (o < PRED && ich < PRIOR) v = rnd(w1[(o * PRIOR + ich) * 3 + tap]);
        Wr1[t] = __float2half_rn(v);
    } else if (t < N1 + N2) {
        t -= N1;
        int tap = t / (192 * 192), rem = t % (192 * 192);
        int o = rem / 192, ich = rem % 192;
        float v = 0.f;
        if (o < PRED && ich < PRED) v = rnd(w2[(o * PRED + ich) * 3 + tap]);
        Wr2[t] = __float2half_rn(v);
    }
}

__global__ void k_trT(const float* __restrict__ s, __half* __restrict__ d)
{
    __shared__ float t[32][33];
    int x0 = blockIdx.x * 32, y0 = blockIdx.y * 32;
    for (int i = threadIdx.y; i < 32; i += 8)
        t[i][threadIdx.x] = s[(long)(y0 + i) * POSE + x0 + threadIdx.x];
    __syncthreads();
    for (int i = threadIdx.y; i < 32; i += 8)
        d[(long)(x0 + i) * POSE + y0 + threadIdx.x] = __float2half_rn(rnd(t[threadIdx.x][i]));
}

__global__ void reduce2(const float* __restrict__ part, int S,
                        const float* __restrict__ ba, const float* __restrict__ bb,
                        float* __restrict__ oa, float* __restrict__ ob,
                        __half* __restrict__ oah, __half* __restrict__ obh)
{
    const int MN = BSZ * 1536;
    int i = blockIdx.x * blockDim.x + threadIdx.x;
    if (i >= MN) return;
    float s = 0.f;
    for (int z = 0; z < S; z++) s += part[(long)z * MN + i];
    int m = i / 1536, n = i - m * 1536;
    if (n < 768) {
        s += ba[n];
        if (oa)  oa[m * 768 + n] = s;
        if (oah) oah[m * 768 + n] = __float2half_rn(rnd(s));
    } else {
        int nn = n - 768;
        s += bb[nn];
        if (ob)  ob[m * 768 + nn] = s;
        if (obh) obh[m * 768 + nn] = __float2half_rn(rnd(s));
    }
}

__global__ void reduce_wch(const float* __restrict__ part,
                           __half* __restrict__ Wf, int MN, int S)
{
    int i = blockIdx.x * blockDim.x + threadIdx.x;
    if (i >= MN) return;
    float s = 0.f;
    for (int z = 0; z < S; z++) s += part[(long)z * MN + i];
    Wf[i] = __float2half_rn(rnd(s));
}

__global__ void k_bc(const float* __restrict__ w2, const float* __restrict__ b1,
                     const float* __restrict__ b2, float* __restrict__ bc)
{
    int w = (blockIdx.x * blockDim.x + threadIdx.x) >> 5;
    int lane = threadIdx.x & 31;
    if (w >= POSE) return;
    float s = 0.f;
    for (int m = lane; m < POSE; m += 32) s += w2[(long)w * POSE + m] * b1[m];
    s = warp_sum(s);
    if (lane == 0) bc[w] = s + b2[w];
}

__global__ void k_tmm(const float* __restrict__ w1, const float* __restrict__ b1,
                      const float* __restrict__ w2, const float* __restrict__ b2,
                      float* __restrict__ Wt, float* __restrict__ bt)
{
    int idx = blockIdx.x * blockDim.x + threadIdx.x;
    const int KK = CHUNK * POSE;
    if (idx < CHUNK * KK) {
        int c = idx / KK, k = idx - c * KK;
        float s = 0.f;
        #pragma unroll
        for (int m = 0; m < CHUNK; m++) s += w2[c * CHUNK + m] * w1[(long)m * KK + k];
        Wt[idx] = s;
    }
    if (idx < CHUNK) {
        float s = b2[idx];
        #pragma unroll
        for (int m = 0; m < CHUNK; m++) s += w2[idx * CHUNK + m] * b1[m];
        bt[idx] = s;
    }
}

__global__ __launch_bounds__(320)
void gate_penc(float* __restrict__ p, const float* __restrict__ mem,
               const float* __restrict__ Wt, const float* __restrict__ bt,
               float* __restrict__ penc)
{
    __shared__ float sm[POSE];
    __shared__ float chunk[CHUNK * POSE];
    __shared__ float sig[CHUNK];
    const int b = blockIdx.x, t = threadIdx.x;
    float* pb = p + (long)b * PRED * POSE;
    for (int i = t; i < POSE; i += 320) sm[i] = mem[(long)b * POSE + i];
    for (int i = t; i < CHUNK * POSE; i += 320) chunk[i] = pb[i];
    __syncthreads();
    const int w = t >> 5, lane = t & 31;
    float s = 0.f;
    for (int d = lane; d < POSE; d += 32) s += sm[d] * chunk[w * POSE + d];
    s = warp_sum(s);
    if (lane == 0) sig[w] = 1.f / (1.f + expf(-s));
    __syncthreads();
    for (int i = t; i < CHUNK * POSE; i += 320) {
        int c = i / POSE, d = i - c * POSE;
        float g = sig[c];
        chunk[i] = g * chunk[i] + (1.f - g) * sm[d];
    }
    __syncthreads();
    for (int i = t; i < CHUNK * POSE; i += 320) pb[i] = rnd(chunk[i]);
    float acc = 0.f;
    for (int k = lane; k < CHUNK * POSE; k += 32) acc += chunk[k] * Wt[(long)w * CHUNK * POSE + k];
    acc = warp_sum(acc);
    if (lane == 0) penc[b * CHUNK + w] = acc + bt[w];
}

__global__ void k_M(const float* __restrict__ mem2, const float* __restrict__ penc,
                    float* __restrict__ Mo)
{
    __shared__ float pe[BSZ * CHUNK];
    const int t = threadIdx.x;
    for (int i = t; i < BSZ * CHUNK; i += 256) pe[i] = penc[i];
    __syncthreads();
    int d = blockIdx.x * 256 + t;
    float acc[CHUNK];
    #pragma unroll
    for (int c = 0; c < CHUNK; c++) acc[c] = 0.f;
    for (int b = 0; b < BSZ; b++) {
        float mv = mem2[(long)b * POSE + d];
        #pragma unroll
        for (int c = 0; c < CHUNK; c++) acc[c] = fmaf(mv, pe[b * CHUNK + c], acc[c]);
    }
    #pragma unroll
    for (int c = 0; c < CHUNK; c++) Mo[d * CHUNK + c] = acc[c];
}

__global__ __launch_bounds__(320)
void k_score2(float* __restrict__ p, const float* __restrict__ mem2,
              const float* __restrict__ Mo, __half* __restrict__ pf)
{
    __shared__ float sm[POSE];
    __shared__ float sc[CHUNK];
    __shared__ float softs[CHUNK];
    const int b = blockIdx.x, t = threadIdx.x;
    for (int i = t; i < POSE; i += 320) sm[i] = mem2[(long)b * POSE + i];
    __syncthreads();
    const int w = t >> 5, lane = t & 31;
    float s = 0.f;
    for (int d = lane; d < POSE; d += 32) s += sm[d] * Mo[d * CHUNK + w];
    s = warp_sum(s);
    if (lane == 0) sc[w] = s;
    __syncthreads();
    if (t == 0) {
        float mx = sc[0];
        #pragma unroll
        for (int c = 1; c < CHUNK; c++) mx = fmaxf(mx, sc[c]);
        float ssum = 0.f;
        #pragma unroll
        for (int c = 0; c < CHUNK; c++) { float e = expf(sc[c] - mx); softs[c] = e; ssum += e; }
        float inv = 1.f / ssum;
        #pragma unroll
        for (int c = 0; c < CHUNK; c++) softs[c] *= inv;
    }
    __syncthreads();
    float* pb = p + (long)b * PRED * POSE;
    __half* pfb = pf + (long)b * PRED * POSE;
    for (int i = t; i < CHUNK * POSE; i += 320) {
        int c = i / POSE;
        float v = rnd(pb[i] * (1.f + softs[c]));
        pb[i] = v;
        pfb[i] = __float2half_rn(v);
    }
}

// ---------------- launch ----------------
extern "C" void kernel_launch(void* const* d_in, const int* in_sizes, int n_in,
                              void* d_out, int out_size)
{
    const float* x       = (const float*)d_in[0];
    const float* conv1_w = (const float*)d_in[1];
    const float* conv1_b = (const float*)d_in[2];
    const float* bn1_g   = (const float*)d_in[3];
    const float* bn1_b   = (const float*)d_in[4];
    const float* bn1_m   = (const float*)d_in[5];
    const float* bn1_v   = (const float*)d_in[6];
    const float* conv2_w = (const float*)d_in[7];
    const float* conv2_b = (const float*)d_in[8];
    const float* bn2_g   = (const float*)d_in[9];
    const float* bn2_b   = (const float*)d_in[10];
    const float* bn2_m   = (const float*)d_in[11];
    const float* bn2_v   = (const float*)d_in[12];
    const float* sp_w1   = (const float*)d_in[13];
    const float* sp_b1   = (const float*)d_in[14];
    const float* sp_w2   = (const float*)d_in[15];
    const float* sp_b2   = (const float*)d_in[16];
    const float* tmc_w1  = (const float*)d_in[17];
    const float* tmc_b1  = (const float*)d_in[18];
    const float* tmc_w2  = (const float*)d_in[19];
    const float* tmc_b2  = (const float*)d_in[20];
    const float* tmm_w1  = (const float*)d_in[21];
    const float* tmm_b1  = (const float*)d_in[22];
    const float* tmm_w2  = (const float*)d_in[23];
    const float* tmm_b2  = (const float*)d_in[24];
    const float* post_w1 = (const float*)d_in[25];
    const float* post_b1 = (const float*)d_in[26];
    const float* post_w2 = (const float*)d_in[27];
    const float* post_b2 = (const float*)d_in[28];

    float *p, *bc, *Wt, *bt, *mem, *mem2, *penc, *Mm, *part;
    __half *p1T, *xT, *wr1, *wr2, *w1cat, *sw2, *tw2, *pw2, *pw1T;
    __half *hsp, *htm, *xf, *pf, *Wcf;
    cudaGetSymbolAddress((void**)&p,     g_p);
    cudaGetSymbolAddress((void**)&p1T,   g_p1T);
    cudaGetSymbolAddress((void**)&xT,    g_xT);
    cudaGetSymbolAddress((void**)&wr1,   g_wr1);
    cudaGetSymbolAddress((void**)&wr2,   g_wr2);
    cudaGetSymbolAddress((void**)&w1cat, g_w1cat);
    cudaGetSymbolAddress((void**)&sw2,   g_sw2);
    cudaGetSymbolAddress((void**)&tw2,   g_tw2);
    cudaGetSymbolAddress((void**)&pw2,   g_pw2);
    cudaGetSymbolAddress((void**)&pw1T,  g_pw1T);
    cudaGetSymbolAddress((void**)&bc,    g_bc);
    cudaGetSymbolAddress((void**)&Wt,    g_Wt);
    cudaGetSymbolAddress((void**)&bt,    g_bt);
    cudaGetSymbolAddress((void**)&hsp,   g_hsp);
    cudaGetSymbolAddress((void**)&htm,   g_htm);
    cudaGetSymbolAddress((void**)&mem,   g_mem);
    cudaGetSymbolAddress((void**)&mem2,  g_mem2);
    cudaGetSymbolAddress((void**)&penc,  g_penc);
    cudaGetSymbolAddress((void**)&Mm,    g_Mmat);
    cudaGetSymbolAddress((void**)&part,  g_part);
    cudaGetSymbolAddress((void**)&xf,    g_xf);
    cudaGetSymbolAddress((void**)&pf,    g_pf);
    cudaGetSymbolAddress((void**)&Wcf,   g_Wcf);

    const int SMEM_G    = 4 * 128 * 40 * 2 * 2;                // 81920
    const int SMEM_CONV = 3 * (288 * 24 + 136 * 24) * 2;       // 61056
    const int SMEM_HP   = 4 * (128 * 40 + 256 * 40) * 2;       // 122880
    cudaFuncSetAttribute(ghemm,        cudaFuncAttributeMaxDynamicSharedMemorySize, SMEM_G);
    cudaFuncSetAttribute(final_hp,     cudaFuncAttributeMaxDynamicSharedMemorySize, SMEM_HP);
    cudaFuncSetAttribute(conv_hp<60>,  cudaFuncAttributeMaxDynamicSharedMemorySize, SMEM_CONV);
    cudaFuncSetAttribute(conv_hp<180>, cudaFuncAttributeMaxDynamicSharedMemorySize, SMEM_CONV);

    // 0,1: conv prep
    k_convw<<<(3*192*64 + 3*192*192 + 255) / 256, 256>>>(conv1_w, conv2_w, wr1, wr2);
    k_trx<<<dim3(24, BSZ), dim3(32, 8)>>>(x, xT, p1T);

    // 2: conv1 (-> p1T)   3: conv2 (-> p fp32 + pf fp16), ncu capture idx 3
    conv_hp<60><<<dim3(6, 2, BSZ), 256, SMEM_CONV>>>(xT, wr1, conv1_b,
        bn1_g, bn1_b, bn1_m, bn1_v, nullptr, nullptr, p1T);
    conv_hp<180><<<dim3(6, 2, BSZ), 256, SMEM_CONV>>>(p1T, wr2, conv2_b,
        bn2_g, bn2_b, bn2_m, bn2_v, p, pf, nullptr);

    // 4: fp16 round-copies of GEMM operands
    R6 r;
    const float* srcs[6] = { x, sp_w1, tmc_w1, sp_w2, tmc_w2, post_w2 };
    __half* dsts[6]      = { xf, w1cat, w1cat + POSE * CHUNK * POSE, sw2, tw2, pw2 };
    int ns[6] = { BSZ*PRIOR*POSE, POSE*CHUNK*POSE, POSE*CHUNK*POSE,
                  POSE*POSE, POSE*POSE, POSE*POSE };
    int total4 = 0;
    for (int i = 0; i < 6; i++) {
        r.s[i] = (const float4*)srcs[i]; r.d[i] = (__half2*)dsts[i];
        r.n4[i] = ns[i] / 4; total4 += ns[i] / 4;
    }
    k_round_h<<<(total4 + 255) / 256, 256>>>(r, total4);

    // 5-7: small weight prep
    k_trT<<<dim3(24, 24), dim3(32, 8)>>>(post_w1, pw1T);
    k_bc<<<96, 256>>>(post_w2, post_b1, post_b2, bc);
    k_tmm<<<300, 256>>>(tmm_w1, tmm_b1, tmm_w2, tmm_b2, Wt, bt);

    // 8,9: merged SP/TMC layer-1 (fp16, split-K 16)
    const __half* tail = xf + (PRIOR - CHUNK) * POSE;
    ghemm<<<dim3(12, 2, 16), 256, SMEM_G>>>(tail, (long)PRIOR * POSE, w1cat,
        (long)CHUNK * POSE, part, BSZ, 2 * POSE, CHUNK * POSE, 480, 1536, 0);
    reduce2<<<(BSZ * 1536 + 255) / 256, 256>>>(part, 16, sp_b1, tmc_b1,
        nullptr, nullptr, hsp, htm);
    // 10-12: layer-2 (fp16)
    ghemm<<<dim3(6, 2, 8), 256, SMEM_G>>>(hsp, POSE, sw2, POSE,
        part, BSZ, POSE, POSE, 96, 1536, 0);
    ghemm<<<dim3(6, 2, 8), 256, SMEM_G>>>(htm, POSE, tw2, POSE,
        part, BSZ, POSE, POSE, 96, 1536, 768);
    reduce2<<<(BSZ * 1536 + 255) / 256, 256>>>(part, 8, sp_b2, tmc_b2,
        mem, mem2, nullptr, nullptr);

    // 13,14: Wc = post_w2 @ post_w1 (fp16) -> Wcf
    ghemm<<<dim3(6, 6, 8), 256, SMEM_G>>>(pw2, POSE, pw1T, POSE,
        part, POSE, POSE, POSE, 96, POSE, 0);
    reduce_wch<<<(POSE * POSE + 255) / 256, 256>>>(part, Wcf, POSE * POSE, 8);

    // 15-17: memory nets
    gate_penc<<<BSZ, 320>>>(p, mem, Wt, bt, penc);
    k_M<<<3, 256>>>(mem2, penc, Mm);
    k_score2<<<BSZ, 320>>>(p, mem2, Mm, pf);

    // 18: fp16 final GEMM -> d_out
    final_hp<<<dim3(3, 480), 256, SMEM_HP>>>(xf, pf, Wcf, bc, (float*)d_out);
}

// round 14
// speedup vs baseline: 1.3495x; 1.0521x over previous
#include <cuda_runtime.h>
#include <cuda_fp16.h>
#include <math.h>

#define BSZ    256
#define PRIOR  60
#define FRAMES 240
#define POSE   768
#define PRED   180
#define CHUNK  10
#define EPSBN  1e-5f

__device__ float  g_pch [BSZ * CHUNK * POSE];   // fp32 gated chunk rows (0..9)
__device__ __half g_p1T [BSZ * POSE * 192];     // conv1 out, transposed [b][pos][ich]
__device__ __half g_xT  [BSZ * POSE * 64];      // x transposed  [b][pos][ich]
__device__ __half g_wr1 [3 * 192 * 64];
__device__ __half g_wr2 [3 * 192 * 192];
__device__ __half g_w1cat[2 * POSE * CHUNK * POSE];
__device__ __half g_sw2 [POSE * POSE];
__device__ __half g_tw2 [POSE * POSE];
__device__ __half g_pw2 [POSE * POSE];
__device__ __half g_pw1T[POSE * POSE];
__device__ float  g_bc  [POSE];
__device__ float  g_Wt  [CHUNK * CHUNK * POSE];
__device__ float  g_bt  [CHUNK];
__device__ __half g_hsp [BSZ * POSE];
__device__ __half g_htm [BSZ * POSE];
__device__ float  g_mem [BSZ * POSE];
__device__ float  g_mem2[BSZ * POSE];
__device__ float  g_penc[BSZ * CHUNK];
__device__ float  g_Mmat[POSE * CHUNK];
__device__ float  g_part[16 * 256 * 1536];
__device__ __half g_xf [BSZ * PRIOR * POSE];
__device__ __half g_pf [BSZ * PRED * POSE];
__device__ __half g_Wcf[POSE * POSE];

__device__ __forceinline__ float warp_sum(float v) {
    #pragma unroll
    for (int o = 16; o; o >>= 1) v += __shfl_xor_sync(0xffffffffu, v, o);
    return v;
}
__device__ __forceinline__ unsigned f2tf(float x) {
    unsigned u;
    asm("cvt.rna.tf32.f32 %0, %1;" : "=r"(u) : "f"(x));
    return u;
}
__device__ __forceinline__ float rnd(float x) { return __uint_as_float(f2tf(x)); }

__device__ __forceinline__ void cp16(unsigned d, const void* s, bool p) {
    asm volatile("cp.async.ca.shared.global [%0], [%1], 16, %2;"
                 :: "r"(d), "l"(s), "r"(p ? 16 : 0));
}
#define CP_COMMIT() asm volatile("cp.async.commit_group;" ::: "memory")
#define CP_WAIT1()  asm volatile("cp.async.wait_group 1;" ::: "memory")
#define CP_WAIT2()  asm volatile("cp.async.wait_group 2;" ::: "memory")

__device__ __forceinline__ unsigned s2u(const void* p) {
    unsigned a;
    asm("{ .reg .u64 t; cvta.to.shared.u64 t, %1; cvt.u32.u64 %0, t; }" : "=r"(a) : "l"(p));
    return a;
}
__device__ __forceinline__ void ldsm4(unsigned &r0, unsigned &r1, unsigned &r2, unsigned &r3,
                                      unsigned addr)
{
    asm volatile("ldmatrix.sync.aligned.m8n8.x4.shared.b16 {%0,%1,%2,%3}, [%4];"
                 : "=r"(r0), "=r"(r1), "=r"(r2), "=r"(r3) : "r"(addr));
}
#define MMA_FP16(acc, a, b0v, b1v) \
    asm volatile( \
        "mma.sync.aligned.m16n8k16.row.col.f32.f16.f16.f32 " \
        "{%0,%1,%2,%3},{%4,%5,%6,%7},{%8,%9},{%0,%1,%2,%3};" \
        : "+f"((acc)[0]), "+f"((acc)[1]), "+f"((acc)[2]), "+f"((acc)[3]) \
        : "r"((a)[0]), "r"((a)[1]), "r"((a)[2]), "r"((a)[3]), \
          "r"(b0v), "r"(b1v))

// ---------------------------------------------------------------------------
// Generic fp16 GEMM: A [M,K], B [N,K], split-K fp32 partials. 128x128 tile,
// warp 64x32, K-slab 32, 4-stage, 2 CTAs/SM. (R13-proven)
// ---------------------------------------------------------------------------
__global__ __launch_bounds__(256, 2)
void ghemm(const __half* __restrict__ A, long lda,
           const __half* __restrict__ B, long ldb,
           float* __restrict__ Cpart,
           int M, int N, int K, int kchunk, int ldcN, int coffs)
{
    extern __shared__ unsigned sh[];
    unsigned shbase = s2u(sh);
    const unsigned STG = 128u * 40u * 2u;
    const unsigned bsoff = 4u * STG;

    const int tid = threadIdx.x;
    const int warpid = tid >> 5, lane = tid & 31;
    const int mbase = (warpid >> 2) * 64, nbase = (warpid & 3) * 32;
    const int quad = lane >> 3, qr = lane & 7;
    const int bm = blockIdx.y * 128, bn = blockIdx.x * 128;
    const int k0base = blockIdx.z * kchunk;
    const int nk = kchunk >> 5;

    const unsigned aAq = shbase + (((mbase + (quad & 1) * 8 + qr) * 40 + (quad >> 1) * 8) * 2);
    const unsigned aBq = shbase + bsoff + (((nbase + (quad >> 1) * 8 + qr) * 40 + (quad & 1) * 8) * 2);

    float acc[4][4][4];
    #pragma unroll
    for (int mt = 0; mt < 4; mt++)
        #pragma unroll
        for (int nt = 0; nt < 4; nt++)
            #pragma unroll
            for (int r = 0; r < 4; r++) acc[mt][nt][r] = 0.f;

    auto load = [&](int st, int k0) {
        #pragma unroll
        for (int i = 0; i < 2; i++) {
            int idx = tid + i * 256, r = idx >> 2, kq = idx & 3;
            cp16(shbase + st * STG + (r * 40 + kq * 8) * 2,
                 A + (long)(bm + r) * lda + k0 + kq * 8, bm + r < M);
            cp16(shbase + bsoff + st * STG + (r * 40 + kq * 8) * 2,
                 B + (long)(bn + r) * ldb + k0 + kq * 8, bn + r < N);
        }
    };
    #pragma unroll
    for (int s = 0; s < 3; s++) {
        if (s < nk) load(s, k0base + s * 32);
        CP_COMMIT();
    }
    for (int i = 0; i < nk; i++) {
        CP_WAIT2();
        __syncthreads();
        if (i + 3 < nk) load((i + 3) & 3, k0base + (i + 3) * 32);
        CP_COMMIT();
        int st = i & 3;
        unsigned aA = aAq + st * STG, aB = aBq + st * STG;
        #pragma unroll
        for (int kh = 0; kh < 2; kh++) {
            unsigned a[4][4], b[2][4];
            #pragma unroll
            for (int mt = 0; mt < 4; mt++)
                ldsm4(a[mt][0], a[mt][1], a[mt][2], a[mt][3],
                      aA + (mt * 16 * 40 + kh * 16) * 2);
            #pragma unroll
            for (int np = 0; np < 2; np++)
                ldsm4(b[np][0], b[np][1], b[np][2], b[np][3],
                      aB + (np * 16 * 40 + kh * 16) * 2);
            #pragma unroll
            for (int mt = 0; mt < 4; mt++)
                #pragma unroll
                for (int nt = 0; nt < 4; nt++)
                    MMA_FP16(acc[mt][nt], a[mt],
                             b[nt >> 1][(nt & 1) * 2], b[nt >> 1][(nt & 1) * 2 + 1]);
        }
    }
    float* Cz = Cpart + (long)blockIdx.z * M * ldcN;
    #pragma unroll
    for (int mt = 0; mt < 4; mt++) {
        int gm0 = bm + mbase + mt * 16 + (lane >> 2);
        #pragma unroll
        for (int nt = 0; nt < 4; nt++) {
            int gn0 = bn + nbase + nt * 8 + (lane & 3) * 2;
            if (gm0 < M && gn0 < N) {
                Cz[(long)gm0 * ldcN + coffs + gn0]     = acc[mt][nt][0];
                Cz[(long)gm0 * ldcN + coffs + gn0 + 1] = acc[mt][nt][1];
            }
            if (gm0 + 8 < M && gn0 < N) {
                Cz[(long)(gm0 + 8) * ldcN + coffs + gn0]     = acc[mt][nt][2];
                Cz[(long)(gm0 + 8) * ldcN + coffs + gn0 + 1] = acc[mt][nt][3];
            }
        }
    }
}

// ---------------------------------------------------------------------------
// fp16 tap-decomposed Conv1d(k=3,p=1). X k-major [b][pos][ICHP] halves.
// Epilogues: OutT (transposed fp16, conv1) else OutH fp16 ONLY (conv2).
// ---------------------------------------------------------------------------
template<int ICH>
__global__ __launch_bounds__(256, 2)
void conv_hp(const __half* __restrict__ X,
             const __half* __restrict__ Wr,
             const float* __restrict__ cb,
             const float* __restrict__ bg, const float* __restrict__ bb,
             const float* __restrict__ bmn, const float* __restrict__ bv,
             __half* __restrict__ OutH, __half* __restrict__ OutT)
{
    constexpr int ICHP = (ICH + 63) & ~63;
    constexpr int NK = ICHP / 16;
    extern __shared__ unsigned sh[];
    unsigned shbase = s2u(sh);
    const unsigned ASTG = 288u * 24u * 2u;
    const unsigned BSTG = 136u * 24u * 2u;
    const unsigned bsoff = 3u * ASTG;

    const int b = blockIdx.z;
    const __half* Xb = X + (long)b * POSE * ICHP;
    const int tid = threadIdx.x;
    const int warpid = tid >> 5, lane = tid & 31;
    const int mbase = (warpid >> 2) * 48, nbase = (warpid & 3) * 32;
    const int quad = lane >> 3, qr = lane & 7;
    const int gid = lane >> 2, tig = lane & 3;
    const int bm = blockIdx.y * 96, bn = blockIdx.x * 128;

    const unsigned aAq = shbase + (((mbase + (quad & 1) * 8 + qr) * 24 + (quad >> 1) * 8) * 2);
    const int bW0 = (int)(bsoff >> 2);

    float acc[3][4][4];
    #pragma unroll
    for (int mt = 0; mt < 3; mt++)
        #pragma unroll
        for (int nt = 0; nt < 4; nt++)
            #pragma unroll
            for (int r = 0; r < 4; r++) acc[mt][nt][r] = 0.f;

    auto load = [&](int st, int k0) {
        #pragma unroll
        for (int i = 0; i < 3; i++) {
            int idx = tid + i * 256;
            if (idx < 576) {
                int tap = idx / 192, rem = idx - tap * 192;
                int m = rem >> 1, j = rem & 1;
                cp16(shbase + st * ASTG + ((tap * 96 + m) * 24 + j * 8) * 2,
                     Wr + ((long)tap * 192 + bm + m) * ICHP + k0 + j * 8, true);
            }
        }
        #pragma unroll
        for (int i = 0; i < 2; i++) {
            int idx = tid + i * 256;
            if (idx < 272) {
                int r = idx >> 1, j = idx & 1;
                int pos = bn - 4 + r;
                bool p = (pos >= 0) && (pos < POSE);
                cp16(shbase + bsoff + st * BSTG + (r * 24 + j * 8) * 2,
                     Xb + (long)(p ? pos : 0) * ICHP + k0 + j * 8, p);
            }
        }
    };
    #pragma unroll
    for (int s = 0; s < 2; s++) {
        if (s < NK) load(s, s * 16);
        CP_COMMIT();
    }
    const unsigned* shu = sh;
    for (int i = 0; i < NK; i++) {
        CP_WAIT1();
        __syncthreads();
        if (i + 2 < NK) load((i + 2) % 3, (i + 2) * 16);
        CP_COMMIT();
        int st = i % 3;
        unsigned aA = aAq + st * ASTG;
        int bW = bW0 + st * (int)(BSTG >> 2);
        #pragma unroll
        for (int t = 0; t < 3; t++) {
            unsigned a[3][4];
            #pragma unroll
            for (int mt = 0; mt < 3; mt++)
                ldsm4(a[mt][0], a[mt][1], a[mt][2], a[mt][3],
                      aA + ((t * 96 + mt * 16) * 24) * 2);
            #pragma unroll
            for (int nt = 0; nt < 4; nt++) {
                int row = nbase + nt * 8 + gid + t + 3;
                unsigned b0 = shu[bW + row * 12 + tig];
                unsigned b1 = shu[bW + row * 12 + tig + 4];
                #pragma unroll
                for (int mt = 0; mt < 3; mt++)
                    MMA_FP16(acc[mt][nt], a[mt], b0, b1);
            }
        }
    }

    #pragma unroll
    for (int mt = 0; mt < 3; mt++) {
        #pragma unroll
        for (int half_ = 0; half_ < 2; half_++) {
            int gm = bm + mbase + mt * 16 + (lane >> 2) + half_ * 8;
            if (gm < PRED) {
                float s  = bg[gm] * rsqrtf(bv[gm] + EPSBN);
                float sht = bb[gm] - bmn[gm] * s;
                float cv = cb[gm];
                #pragma unroll
                for (int nt = 0; nt < 4; nt++) {
                    int gn0 = bn + nbase + nt * 8 + (lane & 3) * 2;
                    float y0 = fmaxf(acc[mt][nt][half_ * 2]     + cv, 0.f);
                    float y1 = fmaxf(acc[mt][nt][half_ * 2 + 1] + cv, 0.f);
                    float v0 = rnd(y0 * s + sht), v1 = rnd(y1 * s + sht);
                    if (OutT) {
                        OutT[((long)b * POSE + gn0)     * 192 + gm] = __float2half_rn(v0);
                        OutT[((long)b * POSE + gn0 + 1) * 192 + gm] = __float2half_rn(v1);
                    } else {
                        long o = ((long)b * PRED + gm) * POSE + gn0;
                        *(__half2*)(OutH + o) = __halves2half2(__float2half_rn(v0),
                                                               __float2half_rn(v1));
                    }
                }
            }
        }
    }
}

// ---------------------------------------------------------------------------
// fp16 final GEMM (R11-proven): CTA 128x256, warp 64x64, K-slab 32, 4-stage.
// ---------------------------------------------------------------------------
__global__ __launch_bounds__(256)
void final_hp(const __half* __restrict__ xf, const __half* __restrict__ pf,
              const __half* __restrict__ Wf, const float* __restrict__ bias,
              float* __restrict__ C)
{
    extern __shared__ unsigned sh[];
    __shared__ const __half* rowp[128];
    unsigned shbase = s2u(sh);
    const unsigned ASTG = 128u * 40u * 2u;
    const unsigned BSTG = 256u * 40u * 2u;
    const unsigned bsoff = 4u * ASTG;

    const int tid = threadIdx.x;
    const int warpid = tid >> 5, lane = tid & 31;
    const int mbase = (warpid >> 2) * 64, nbase = (warpid & 3) * 64;
    const int quad = lane >> 3, qr = lane & 7;
    const int bm = blockIdx.y * 128, bn = blockIdx.x * 256;
    const int nk = POSE / 32;

    if (tid < 128) {
        int r = bm + tid;
        int bb_ = r / FRAMES, f = r - bb_ * FRAMES;
        rowp[tid] = (f < PRIOR) ? xf + ((long)bb_ * PRIOR + f) * POSE
                                : pf + ((long)bb_ * PRED + (f - PRIOR)) * POSE;
    }
    __syncthreads();

    const unsigned aAq = shbase + (((mbase + (quad & 1) * 8 + qr) * 40 + (quad >> 1) * 8) * 2);
    const unsigned aBq = shbase + bsoff + (((nbase + (quad >> 1) * 8 + qr) * 40 + (quad & 1) * 8) * 2);

    float acc[4][8][4];
    #pragma unroll
    for (int mt = 0; mt < 4; mt++)
        #pragma unroll
        for (int nt = 0; nt < 8; nt++)
            #pragma unroll
            for (int r = 0; r < 4; r++) acc[mt][nt][r] = 0.f;

    const int m_ = tid >> 2, kq = tid & 3;
    auto load = [&](int st, int k0) {
        int gk = k0 + kq * 8;
        #pragma unroll
        for (int i = 0; i < 2; i++) {
            int m = m_ + i * 64;
            cp16(shbase + st * ASTG + (m * 40 + kq * 8) * 2, rowp[m] + gk, true);
        }
        #pragma unroll
        for (int i = 0; i < 4; i++) {
            int n = m_ + i * 64;
            cp16(shbase + bsoff + st * BSTG + (n * 40 + kq * 8) * 2,
                 Wf + (long)(bn + n) * POSE + gk, true);
        }
    };

    #pragma unroll
    for (int s = 0; s < 3; s++) { load(s, s * 32); CP_COMMIT(); }
    for (int i = 0; i < nk; i++) {
        CP_WAIT2();
        __syncthreads();
        if (i + 3 < nk) load((i + 3) & 3, (i + 3) * 32);
        CP_COMMIT();
        int st = i & 3;
        unsigned aA = aAq + st * ASTG, aB = aBq + st * BSTG;
        #pragma unroll
        for (int kh = 0; kh < 2; kh++) {
            unsigned a[4][4], b[4][4];
            #pragma unroll
            for (int mt = 0; mt < 4; mt++)
                ldsm4(a[mt][0], a[mt][1], a[mt][2], a[mt][3],
                      aA + (mt * 16 * 40 + kh * 16) * 2);
            #pragma unroll
            for (int np = 0; np < 4; np++)
                ldsm4(b[np][0], b[np][1], b[np][2], b[np][3],
                      aB + (np * 16 * 40 + kh * 16) * 2);
            #pragma unroll
            for (int mt = 0; mt < 4; mt++)
                #pragma unroll
                for (int nt = 0; nt < 8; nt++)
                    MMA_FP16(acc[mt][nt], a[mt],
                             b[nt >> 1][(nt & 1) * 2], b[nt >> 1][(nt & 1) * 2 + 1]);
        }
    }

    #pragma unroll
    for (int mt = 0; mt < 4; mt++) {
        int gm0 = bm + mbase + mt * 16 + (lane >> 2);
        #pragma unroll
        for (int nt = 0; nt < 8; nt++) {
            int gn0 = bn + nbase + nt * 8 + (lane & 3) * 2;
            float2 bv = *(const float2*)(bias + gn0);
            float2 v0 = make_float2(acc[mt][nt][0] + bv.x, acc[mt][nt][1] + bv.y);
            float2 v1 = make_float2(acc[mt][nt][2] + bv.x, acc[mt][nt][3] + bv.y);
            *(float2*)(C + (long)gm0 * POSE + gn0)       = v0;
            *(float2*)(C + (long)(gm0 + 8) * POSE + gn0) = v1;
        }
    }
}

// ---------------- prep / glue ----------------
struct R6 { const float4* s[6]; __half2* d[6]; int n4[6]; };
__global__ void k_round_h(R6 r, int total4)
{
    int gid = blockIdx.x * blockDim.x + threadIdx.x;
    if (gid >= total4) return;
    #pragma unroll
    for (int k = 0; k < 6; k++) {
        if (gid < r.n4[k]) {
            float4 v = r.s[k][gid];
            r.d[k][gid * 2]     = __halves2half2(__float2half_rn(rnd(v.x)),
                                                 __float2half_rn(rnd(v.y)));
            r.d[k][gid * 2 + 1] = __halves2half2(__float2half_rn(rnd(v.z)),
                                                 __float2half_rn(rnd(v.w)));
            return;
        }
        gid -= r.n4[k];
    }
}

// x [b][60][768] -> xT fp16 [b][768][64]; also zero p1T pad cols 180-191.
__global__ void k_trx(const float* __restrict__ x, __half* __restrict__ xT,
                      __half* __restrict__ p1T)
{
    __shared__ float t[64][33];
    int b = blockIdx.y, pos0 = blockIdx.x * 32;
    int tx = threadIdx.x, ty = threadIdx.y;
    for (int ich = ty; ich < 64; ich += 8)
        t[ich][tx] = (ich < PRIOR) ? rnd(x[((long)b * PRIOR + ich) * POSE + pos0 + tx]) : 0.f;
    __syncthreads();
    int tid = ty * 32 + tx;
    for (int e = tid; e < 32 * 64; e += 256) {
        int r = e >> 6, ich = e & 63;
        xT[((long)b * POSE + pos0 + r) * 64 + ich] = __float2half_rn(t[ich][r]);
    }
    for (int e = tid; e < 32 * 12; e += 256) {
        int r = e / 12, j = e - r * 12;
        p1T[((long)b * POSE + pos0 + r) * 192 + 180 + j] = __float2half_rn(0.f);
    }
}

__global__ void k_convw(const float* __restrict__ w1, const float* __restrict__ w2,
                        __half* __restrict__ Wr1, __half* __restrict__ Wr2)
{
    const int N1 = 3 * 192 * 64, N2 = 3 * 192 * 192;
    int t = blockIdx.x * blockDim.x + threadIdx.x;
    if (t < N1) {
        int tap = t / (192 * 64), rem = t % (192 * 64);
        int o = rem / 64, ich = rem % 64;
        float v = 0.f;
        if (o < PRED && ich < PRIOR) v = rnd(w1[(o * PRIOR + ich) * 3 + tap]);
        Wr1[t] = __float2half_rn(v);
    } else if (t < N1 + N2) {
        t -= N1;
        int tap = t / (192 * 192), rem = t % (192 * 192);
        int o = rem / 192, ich = rem % 192;
        float v = 0.f;
        if (o < PRED && ich < PRED) v = rnd(w2[(o * PRED + ich) * 3 + tap]);
        Wr2[t] = __float2half_rn(v);
    }
}

__global__ void k_trT(const float* __restrict__ s, __half* __restrict__ d)
{
    __shared__ float t[32][33];
    int x0 = blockIdx.x * 32, y0 = blockIdx.y * 32;
    for (int i = threadIdx.y; i < 32; i += 8)
        t[i][threadIdx.x] = s[(long)(y0 + i) * POSE + x0 + threadIdx.x];
    __syncthreads();
    for (int i = threadIdx.y; i < 32; i += 8)
        d[(long)(x0 + i) * POSE + y0 + threadIdx.x] = __float2half_rn(rnd(t[threadIdx.x][i]));
}

__global__ void reduce2(const float* __restrict__ part, int S,
                        const float* __restrict__ ba, const float* __restrict__ bb,
                        float* __restrict__ oa, float* __restrict__ ob,
                        __half* __restrict__ oah, __half* __restrict__ obh)
{
    const int MN = BSZ * 1536;
    int i = blockIdx.x * blockDim.x + threadIdx.x;
    if (i >= MN) return;
    float s = 0.f;
    for (int z = 0; z < S; z++) s += part[(long)z * MN + i];
    int m = i / 1536, n = i - m * 1536;
    if (n < 768) {
        s += ba[n];
        if (oa)  oa[m * 768 + n] = s;
        if (oah) oah[m * 768 + n] = __float2half_rn(rnd(s));
    } else {
        int nn = n - 768;
        s += bb[nn];
        if (ob)  ob[m * 768 + nn] = s;
        if (obh) obh[m * 768 + nn] = __float2half_rn(rnd(s));
    }
}

__global__ void reduce_wch(const float* __restrict__ part,
                           __half* __restrict__ Wf, int MN, int S)
{
    int i = blockIdx.x * blockDim.x + threadIdx.x;
    if (i >= MN) return;
    float s = 0.f;
    for (int z = 0; z < S; z++) s += part[(long)z * MN + i];
    Wf[i] = __float2half_rn(rnd(s));
}

__global__ void k_bc(const float* __restrict__ w2, const float* __restrict__ b1,
                     const float* __restrict__ b2, float* __restrict__ bc)
{
    int w = (blockIdx.x * blockDim.x + threadIdx.x) >> 5;
    int lane = threadIdx.x & 31;
    if (w >= POSE) return;
    float s = 0.f;
    for (int m = lane; m < POSE; m += 32) s += w2[(long)w * POSE + m] * b1[m];
    s = warp_sum(s);
    if (lane == 0) bc[w] = s + b2[w];
}

__global__ void k_tmm(const float* __restrict__ w1, const float* __restrict__ b1,
                      const float* __restrict__ w2, const float* __restrict__ b2,
                      float* __restrict__ Wt, float* __restrict__ bt)
{
    int idx = blockIdx.x * blockDim.x + threadIdx.x;
    const int KK = CHUNK * POSE;
    if (idx < CHUNK * KK) {
        int c = idx / KK, k = idx - c * KK;
        float s = 0.f;
        #pragma unroll
        for (int m = 0; m < CHUNK; m++) s += w2[c * CHUNK + m] * w1[(long)m * KK + k];
        Wt[idx] = s;
    }
    if (idx < CHUNK) {
        float s = b2[idx];
        #pragma unroll
        for (int m = 0; m < CHUNK; m++) s += w2[idx * CHUNK + m] * b1[m];
        bt[idx] = s;
    }
}

// gate: reads chunk rows from pf (fp16 == tf32-rounded exactly), writes gated
// fp32 chunk to pch, penc out.
__global__ __launch_bounds__(320)
void gate_penc(const __half* __restrict__ pf, const float* __restrict__ mem,
               const float* __restrict__ Wt, const float* __restrict__ bt,
               float* __restrict__ pch, float* __restrict__ penc)
{
    __shared__ float sm[POSE];
    __shared__ float chunk[CHUNK * POSE];
    __shared__ float sig[CHUNK];
    const int b = blockIdx.x, t = threadIdx.x;
    const __half* pfb = pf + (long)b * PRED * POSE;
    for (int i = t; i < POSE; i += 320) sm[i] = mem[(long)b * POSE + i];
    for (int i = t; i < CHUNK * POSE; i += 320) chunk[i] = __half2float(pfb[i]);
    __syncthreads();
    const int w = t >> 5, lane = t & 31;
    float s = 0.f;
    for (int d = lane; d < POSE; d += 32) s += sm[d] * chunk[w * POSE + d];
    s = warp_sum(s);
    if (lane == 0) sig[w] = 1.f / (1.f + expf(-s));
    __syncthreads();
    float* pcb = pch + (long)b * CHUNK * POSE;
    for (int i = t; i < CHUNK * POSE; i += 320) {
        int c = i / POSE, d = i - c * POSE;
        float g = sig[c];
        chunk[i] = g * chunk[i] + (1.f - g) * sm[d];
        pcb[i] = rnd(chunk[i]);
    }
    __syncthreads();
    float acc = 0.f;
    for (int k = lane; k < CHUNK * POSE; k += 32) acc += chunk[k] * Wt[(long)w * CHUNK * POSE + k];
    acc = warp_sum(acc);
    if (lane == 0) penc[b * CHUNK + w] = acc + bt[w];
}

__global__ void k_M(const float* __restrict__ mem2, const float* __restrict__ penc,
                    float* __restrict__ Mo)
{
    __shared__ float pe[BSZ * CHUNK];
    const int t = threadIdx.x;
    for (int i = t; i < BSZ * CHUNK; i += 256) pe[i] = penc[i];
    __syncthreads();
    int d = blockIdx.x * 256 + t;
    float acc[CHUNK];
    #pragma unroll
    for (int c = 0; c < CHUNK; c++) acc[c] = 0.f;
    for (int b = 0; b < BSZ; b++) {
        float mv = mem2[(long)b * POSE + d];
        #pragma unroll
        for (int c = 0; c < CHUNK; c++) acc[c] = fmaf(mv, pe[b * CHUNK + c], acc[c]);
    }
    #pragma unroll
    for (int c = 0; c < CHUNK; c++) Mo[d * CHUNK + c] = acc[c];
}

// score2: reads gated fp32 chunk, writes final chunk rows into pf.
__global__ __launch_bounds__(320)
void k_score2(const float* __restrict__ pch, const float* __restrict__ mem2,
              const float* __restrict__ Mo, __half* __restrict__ pf)
{
    __shared__ float sm[POSE];
    __shared__ float sc[CHUNK];
    __shared__ float softs[CHUNK];
    const int b = blockIdx.x, t = threadIdx.x;
    for (int i = t; i < POSE; i += 320) sm[i] = mem2[(long)b * POSE + i];
    __syncthreads();
    const int w = t >> 5, lane = t & 31;
    float s = 0.f;
    for (int d = lane; d < POSE; d += 32) s += sm[d] * Mo[d * CHUNK + w];
    s = warp_sum(s);
    if (lane == 0) sc[w] = s;
    __syncthreads();
    if (t == 0) {
        float mx = sc[0];
        #pragma unroll
        for (int c = 1; c < CHUNK; c++) mx = fmaxf(mx, sc[c]);
        float ssum = 0.f;
        #pragma unroll
        for (int c = 0; c < CHUNK; c++) { float e = expf(sc[c] - mx); softs[c] = e; ssum += e; }
        float inv = 1.f / ssum;
        #pragma unroll
        for (int c = 0; c < CHUNK; c++) softs[c] *= inv;
    }
    __syncthreads();
    const float* pcb = pch + (long)b * CHUNK * POSE;
    __half* pfb = pf + (long)b * PRED * POSE;
    for (int i = t; i < CHUNK * POSE; i += 320) {
        int c = i / POSE;
        pfb[i] = __float2half_rn(rnd(pcb[i] * (1.f + softs[c])));
    }
}

// ---------------- launch ----------------
extern "C" void kernel_launch(void* const* d_in, const int* in_sizes, int n_in,
                              void* d_out, int out_size)
{
    const float* x       = (const float*)d_in[0];
    const float* conv1_w = (const float*)d_in[1];
    const float* conv1_b = (const float*)d_in[2];
    const float* bn1_g   = (const float*)d_in[3];
    const float* bn1_b   = (const float*)d_in[4];
    const float* bn1_m   = (const float*)d_in[5];
    const float* bn1_v   = (const float*)d_in[6];
    const float* conv2_w = (const float*)d_in[7];
    const float* conv2_b = (const float*)d_in[8];
    const float* bn2_g   = (const float*)d_in[9];
    const float* bn2_b   = (const float*)d_in[10];
    const float* bn2_m   = (const float*)d_in[11];
    const float* bn2_v   = (const float*)d_in[12];
    const float* sp_w1   = (const float*)d_in[13];
    const float* sp_b1   = (const float*)d_in[14];
    const float* sp_w2   = (const float*)d_in[15];
    const float* sp_b2   = (const float*)d_in[16];
    const float* tmc_w1  = (const float*)d_in[17];
    const float* tmc_b1  = (const float*)d_in[18];
    const float* tmc_w2  = (const float*)d_in[19];
    const float* tmc_b2  = (const float*)d_in[20];
    const float* tmm_w1  = (const float*)d_in[21];
    const float* tmm_b1  = (const float*)d_in[22];
    const float* tmm_w2  = (const float*)d_in[23];
    const float* tmm_b2  = (const float*)d_in[24];
    const float* post_w1 = (const float*)d_in[25];
    const float* post_b1 = (const float*)d_in[26];
    const float* post_w2 = (const float*)d_in[27];
    const float* post_b2 = (const float*)d_in[28];

    float *pch, *bc, *Wt, *bt, *mem, *mem2, *penc, *Mm, *part;
    __half *p1T, *xT, *wr1, *wr2, *w1cat, *sw2, *tw2, *pw2, *pw1T;
    __half *hsp, *htm, *xf, *pf, *Wcf;
    cudaGetSymbolAddress((void**)&pch,   g_pch);
    cudaGetSymbolAddress((void**)&p1T,   g_p1T);
    cudaGetSymbolAddress((void**)&xT,    g_xT);
    cudaGetSymbolAddress((void**)&wr1,   g_wr1);
    cudaGetSymbolAddress((void**)&wr2,   g_wr2);
    cudaGetSymbolAddress((void**)&w1cat, g_w1cat);
    cudaGetSymbolAddress((void**)&sw2,   g_sw2);
    cudaGetSymbolAddress((void**)&tw2,   g_tw2);
    cudaGetSymbolAddress((void**)&pw2,   g_pw2);
    cudaGetSymbolAddress((void**)&pw1T,  g_pw1T);
    cudaGetSymbolAddress((void**)&bc,    g_bc);
    cudaGetSymbolAddress((void**)&Wt,    g_Wt);
    cudaGetSymbolAddress((void**)&bt,    g_bt);
    cudaGetSymbolAddress((void**)&hsp,   g_hsp);
    cudaGetSymbolAddress((void**)&htm,   g_htm);
    cudaGetSymbolAddress((void**)&mem,   g_mem);
    cudaGetSymbolAddress((void**)&mem2,  g_mem2);
    cudaGetSymbolAddress((void**)&penc,  g_penc);
    cudaGetSymbolAddress((void**)&Mm,    g_Mmat);
    cudaGetSymbolAddress((void**)&part,  g_part);
    cudaGetSymbolAddress((void**)&xf,    g_xf);
    cudaGetSymbolAddress((void**)&pf,    g_pf);
    cudaGetSymbolAddress((void**)&Wcf,   g_Wcf);

    const int SMEM_G    = 4 * 128 * 40 * 2 * 2;                // 81920
    const int SMEM_CONV = 3 * (288 * 24 + 136 * 24) * 2;       // 61056
    const int SMEM_HP   = 4 * (128 * 40 + 256 * 40) * 2;       // 122880
    cudaFuncSetAttribute(ghemm,        cudaFuncAttributeMaxDynamicSharedMemorySize, SMEM_G);
    cudaFuncSetAttribute(final_hp,     cudaFuncAttributeMaxDynamicSharedMemorySize, SMEM_HP);
    cudaFuncSetAttribute(conv_hp<60>,  cudaFuncAttributeMaxDynamicSharedMemorySize, SMEM_CONV);
    cudaFuncSetAttribute(conv_hp<180>, cudaFuncAttributeMaxDynamicSharedMemorySize, SMEM_CONV);

    // 0,1: conv prep
    k_convw<<<(3*192*64 + 3*192*192 + 255) / 256, 256>>>(conv1_w, conv2_w, wr1, wr2);
    k_trx<<<dim3(24, BSZ), dim3(32, 8)>>>(x, xT, p1T);

    // 2: conv1 (-> p1T)   3: conv2 (-> pf fp16 only), ncu capture idx 3
    conv_hp<60><<<dim3(6, 2, BSZ), 256, SMEM_CONV>>>(xT, wr1, conv1_b,
        bn1_g, bn1_b, bn1_m, bn1_v, nullptr, p1T);
    conv_hp<180><<<dim3(6, 2, BSZ), 256, SMEM_CONV>>>(p1T, wr2, conv2_b,
        bn2_g, bn2_b, bn2_m, bn2_v, pf, nullptr);

    // 4: fp16 round-copies of GEMM operands
    R6 r;
    const float* srcs[6] = { x, sp_w1, tmc_w1, sp_w2, tmc_w2, post_w2 };
    __half* dsts[6]      = { xf, w1cat, w1cat + POSE * CHUNK * POSE, sw2, tw2, pw2 };
    int ns[6] = { BSZ*PRIOR*POSE, POSE*CHUNK*POSE, POSE*CHUNK*POSE,
                  POSE*POSE, POSE*POSE, POSE*POSE };
    int total4 = 0;
    for (int i = 0; i < 6; i++) {
        r.s[i] = (const float4*)srcs[i]; r.d[i] = (__half2*)dsts[i];
        r.n4[i] = ns[i] / 4; total4 += ns[i] / 4;
    }
    k_round_h<<<(total4 + 255) / 256, 256>>>(r, total4);

    // 5-7: small weight prep
    k_trT<<<dim3(24, 24), dim3(32, 8)>>>(post_w1, pw1T);
    k_bc<<<96, 256>>>(post_w2, post_b1, post_b2, bc);
    k_tmm<<<300, 256>>>(tmm_w1, tmm_b1, tmm_w2, tmm_b2, Wt, bt);

    // 8,9: merged SP/TMC layer-1 (fp16, split-K 16)
    const __half* tail = xf + (PRIOR - CHUNK) * POSE;
    ghemm<<<dim3(12, 2, 16), 256, SMEM_G>>>(tail, (long)PRIOR * POSE, w1cat,
        (long)CHUNK * POSE, part, BSZ, 2 * POSE, CHUNK * POSE, 480, 1536, 0);
    reduce2<<<(BSZ * 1536 + 255) / 256, 256>>>(part, 16, sp_b1, tmc_b1,
        nullptr, nullptr, hsp, htm);
    // 10-12: layer-2 (fp16)
    ghemm<<<dim3(6, 2, 8), 256, SMEM_G>>>(hsp, POSE, sw2, POSE,
        part, BSZ, POSE, POSE, 96, 1536, 0);
    ghemm<<<dim3(6, 2, 8), 256, SMEM_G>>>(htm, POSE, tw2, POSE,
        part, BSZ, POSE, POSE, 96, 1536, 768);
    reduce2<<<(BSZ * 1536 + 255) / 256, 256>>>(part, 8, sp_b2, tmc_b2,
        mem, mem2, nullptr, nullptr);

    // 13,14: Wc = post_w2 @ post_w1 (fp16) -> Wcf
    ghemm<<<dim3(6, 6, 8), 256, SMEM_G>>>(pw2, POSE, pw1T, POSE,
        part, POSE, POSE, POSE, 96, POSE, 0);
    reduce_wch<<<(POSE * POSE + 255) / 256, 256>>>(part, Wcf, POSE * POSE, 8);

    // 15-17: memory nets (fp32 p eliminated; chunk rows via pf/pch)
    gate_penc<<<BSZ, 320>>>(pf, mem, Wt, bt, pch, penc);
    k_M<<<3, 256>>>(mem2, penc, Mm);
    k_score2<<<BSZ, 320>>>(pch, mem2, Mm, pf);

    // 18: fp16 final GEMM -> d_out
    final_hp<<<dim3(3, 480), 256, SMEM_HP>>>(xf, pf, Wcf, bc, (float*)d_out);
}

// round 15
// speedup vs baseline: 1.4792x; 1.0962x over previous
#include <cuda_runtime.h>
#include <cuda_fp16.h>
#include <math.h>

#define BSZ    256
#define PRIOR  60
#define FRAMES 240
#define POSE   768
#define PRED   180
#define CHUNK  10
#define EPSBN  1e-5f

__device__ float  g_pch [BSZ * CHUNK * POSE];
__device__ __half g_p1T [BSZ * POSE * 192];
__device__ __half g_xT  [BSZ * POSE * 64];
__device__ __half g_wr1 [3 * 192 * 64];
__device__ __half g_wr2 [3 * 192 * 192];
__device__ __half g_w1cat[2 * POSE * CHUNK * POSE];
__device__ __half g_sw2 [POSE * POSE];
__device__ __half g_tw2 [POSE * POSE];
__device__ __half g_pw2 [POSE * POSE];
__device__ __half g_pw1T[POSE * POSE];
__device__ float  g_bc  [POSE];
__device__ float  g_Wt  [CHUNK * CHUNK * POSE];
__device__ float  g_bt  [CHUNK];
__device__ __half g_hsp [BSZ * POSE];
__device__ __half g_htm [BSZ * POSE];
__device__ float  g_mem [BSZ * POSE];
__device__ float  g_mem2[BSZ * POSE];
__device__ float  g_penc[BSZ * CHUNK];
__device__ float  g_Mmat[POSE * CHUNK];
__device__ float  g_part[16 * 256 * 1536];
__device__ __half g_xf [BSZ * PRIOR * POSE];
__device__ __half g_pf [BSZ * PRED * POSE];
__device__ __half g_Wcf[POSE * POSE];

__device__ __forceinline__ float warp_sum(float v) {
    #pragma unroll
    for (int o = 16; o; o >>= 1) v += __shfl_xor_sync(0xffffffffu, v, o);
    return v;
}
__device__ __forceinline__ unsigned f2tf(float x) {
    unsigned u;
    asm("cvt.rna.tf32.f32 %0, %1;" : "=r"(u) : "f"(x));
    return u;
}
__device__ __forceinline__ float rnd(float x) { return __uint_as_float(f2tf(x)); }

__device__ __forceinline__ void cp16(unsigned d, const void* s, bool p) {
    asm volatile("cp.async.ca.shared.global [%0], [%1], 16, %2;"
                 :: "r"(d), "l"(s), "r"(p ? 16 : 0));
}
#define CP_COMMIT() asm volatile("cp.async.commit_group;" ::: "memory")
#define CP_WAIT1()  asm volatile("cp.async.wait_group 1;" ::: "memory")
#define CP_WAIT2()  asm volatile("cp.async.wait_group 2;" ::: "memory")

__device__ __forceinline__ unsigned s2u(const void* p) {
    unsigned a;
    asm("{ .reg .u64 t; cvta.to.shared.u64 t, %1; cvt.u32.u64 %0, t; }" : "=r"(a) : "l"(p));
    return a;
}
__device__ __forceinline__ void ldsm4(unsigned &r0, unsigned &r1, unsigned &r2, unsigned &r3,
                                      unsigned addr)
{
    asm volatile("ldmatrix.sync.aligned.m8n8.x4.shared.b16 {%0,%1,%2,%3}, [%4];"
                 : "=r"(r0), "=r"(r1), "=r"(r2), "=r"(r3) : "r"(addr));
}
#define MMA_FP16(acc, a, b0v, b1v) \
    asm volatile( \
        "mma.sync.aligned.m16n8k16.row.col.f32.f16.f16.f32 " \
        "{%0,%1,%2,%3},{%4,%5,%6,%7},{%8,%9},{%0,%1,%2,%3};" \
        : "+f"((acc)[0]), "+f"((acc)[1]), "+f"((acc)[2]), "+f"((acc)[3]) \
        : "r"((a)[0]), "r"((a)[1]), "r"((a)[2]), "r"((a)[3]), \
          "r"(b0v), "r"(b1v))

// ---------------------------------------------------------------------------
// Generic fp16 GEMM (R13-proven): A [M,K], B [N,K], split-K fp32 partials.
// ---------------------------------------------------------------------------
__global__ __launch_bounds__(256, 2)
void ghemm(const __half* __restrict__ A, long lda,
           const __half* __restrict__ B, long ldb,
           float* __restrict__ Cpart,
           int M, int N, int K, int kchunk, int ldcN, int coffs)
{
    extern __shared__ unsigned sh[];
    unsigned shbase = s2u(sh);
    const unsigned STG = 128u * 40u * 2u;
    const unsigned bsoff = 4u * STG;

    const int tid = threadIdx.x;
    const int warpid = tid >> 5, lane = tid & 31;
    const int mbase = (warpid >> 2) * 64, nbase = (warpid & 3) * 32;
    const int quad = lane >> 3, qr = lane & 7;
    const int bm = blockIdx.y * 128, bn = blockIdx.x * 128;
    const int k0base = blockIdx.z * kchunk;
    const int nk = kchunk >> 5;

    const unsigned aAq = shbase + (((mbase + (quad & 1) * 8 + qr) * 40 + (quad >> 1) * 8) * 2);
    const unsigned aBq = shbase + bsoff + (((nbase + (quad >> 1) * 8 + qr) * 40 + (quad & 1) * 8) * 2);

    float acc[4][4][4];
    #pragma unroll
    for (int mt = 0; mt < 4; mt++)
        #pragma unroll
        for (int nt = 0; nt < 4; nt++)
            #pragma unroll
            for (int r = 0; r < 4; r++) acc[mt][nt][r] = 0.f;

    auto load = [&](int st, int k0) {
        #pragma unroll
        for (int i = 0; i < 2; i++) {
            int idx = tid + i * 256, r = idx >> 2, kq = idx & 3;
            cp16(shbase + st * STG + (r * 40 + kq * 8) * 2,
                 A + (long)(bm + r) * lda + k0 + kq * 8, bm + r < M);
            cp16(shbase + bsoff + st * STG + (r * 40 + kq * 8) * 2,
                 B + (long)(bn + r) * ldb + k0 + kq * 8, bn + r < N);
        }
    };
    #pragma unroll
    for (int s = 0; s < 3; s++) {
        if (s < nk) load(s, k0base + s * 32);
        CP_COMMIT();
    }
    for (int i = 0; i < nk; i++) {
        CP_WAIT2();
        __syncthreads();
        if (i + 3 < nk) load((i + 3) & 3, k0base + (i + 3) * 32);
        CP_COMMIT();
        int st = i & 3;
        unsigned aA = aAq + st * STG, aB = aBq + st * STG;
        #pragma unroll
        for (int kh = 0; kh < 2; kh++) {
            unsigned a[4][4], b[2][4];
            #pragma unroll
            for (int mt = 0; mt < 4; mt++)
                ldsm4(a[mt][0], a[mt][1], a[mt][2], a[mt][3],
                      aA + (mt * 16 * 40 + kh * 16) * 2);
            #pragma unroll
            for (int np = 0; np < 2; np++)
                ldsm4(b[np][0], b[np][1], b[np][2], b[np][3],
                      aB + (np * 16 * 40 + kh * 16) * 2);
            #pragma unroll
            for (int mt = 0; mt < 4; mt++)
                #pragma unroll
                for (int nt = 0; nt < 4; nt++)
                    MMA_FP16(acc[mt][nt], a[mt],
                             b[nt >> 1][(nt & 1) * 2], b[nt >> 1][(nt & 1) * 2 + 1]);
        }
    }
    float* Cz = Cpart + (long)blockIdx.z * M * ldcN;
    #pragma unroll
    for (int mt = 0; mt < 4; mt++) {
        int gm0 = bm + mbase + mt * 16 + (lane >> 2);
        #pragma unroll
        for (int nt = 0; nt < 4; nt++) {
            int gn0 = bn + nbase + nt * 8 + (lane & 3) * 2;
            if (gm0 < M && gn0 < N) {
                Cz[(long)gm0 * ldcN + coffs + gn0]     = acc[mt][nt][0];
                Cz[(long)gm0 * ldcN + coffs + gn0 + 1] = acc[mt][nt][1];
            }
            if (gm0 + 8 < M && gn0 < N) {
                Cz[(long)(gm0 + 8) * ldcN + coffs + gn0]     = acc[mt][nt][2];
                Cz[(long)(gm0 + 8) * ldcN + coffs + gn0 + 1] = acc[mt][nt][3];
            }
        }
    }
}

// ---------------------------------------------------------------------------
// fp16 tap-decomposed Conv1d(k=3,p=1). X k-major [b][pos][ICHP] halves.
// B fragments now via ldsm4 (rows shifted per tap); pitch-24 conflict-free.
// ---------------------------------------------------------------------------
template<int ICH>
__global__ __launch_bounds__(256, 2)
void conv_hp(const __half* __restrict__ X,
             const __half* __restrict__ Wr,
             const float* __restrict__ cb,
             const float* __restrict__ bg, const float* __restrict__ bb,
             const float* __restrict__ bmn, const float* __restrict__ bv,
             __half* __restrict__ OutH, __half* __restrict__ OutT)
{
    constexpr int ICHP = (ICH + 63) & ~63;
    constexpr int NK = ICHP / 16;
    extern __shared__ unsigned sh[];
    unsigned shbase = s2u(sh);
    const unsigned ASTG = 288u * 24u * 2u;
    const unsigned BSTG = 136u * 24u * 2u;
    const unsigned bsoff = 3u * ASTG;

    const int b = blockIdx.z;
    const __half* Xb = X + (long)b * POSE * ICHP;
    const int tid = threadIdx.x;
    const int warpid = tid >> 5, lane = tid & 31;
    const int mbase = (warpid >> 2) * 48, nbase = (warpid & 3) * 32;
    const int quad = lane >> 3, qr = lane & 7;
    const int bm = blockIdx.y * 96, bn = blockIdx.x * 128;

    const unsigned aAq = shbase + (((mbase + (quad & 1) * 8 + qr) * 24 + (quad >> 1) * 8) * 2);
    // B ldsm base: row = 3 + nbase + (quad>>1)*8 + qr, koff = (quad&1)*8
    const unsigned aBq = shbase + bsoff +
        (((3 + nbase + (quad >> 1) * 8 + qr) * 24 + (quad & 1) * 8) * 2);

    float acc[3][4][4];
    #pragma unroll
    for (int mt = 0; mt < 3; mt++)
        #pragma unroll
        for (int nt = 0; nt < 4; nt++)
            #pragma unroll
            for (int r = 0; r < 4; r++) acc[mt][nt][r] = 0.f;

    auto load = [&](int st, int k0) {
        #pragma unroll
        for (int i = 0; i < 3; i++) {
            int idx = tid + i * 256;
            if (idx < 576) {
                int tap = idx / 192, rem = idx - tap * 192;
                int m = rem >> 1, j = rem & 1;
                cp16(shbase + st * ASTG + ((tap * 96 + m) * 24 + j * 8) * 2,
                     Wr + ((long)tap * 192 + bm + m) * ICHP + k0 + j * 8, true);
            }
        }
        #pragma unroll
        for (int i = 0; i < 2; i++) {
            int idx = tid + i * 256;
            if (idx < 272) {
                int r = idx >> 1, j = idx & 1;
                int pos = bn - 4 + r;
                bool p = (pos >= 0) && (pos < POSE);
                cp16(shbase + bsoff + st * BSTG + (r * 24 + j * 8) * 2,
                     Xb + (long)(p ? pos : 0) * ICHP + k0 + j * 8, p);
            }
        }
    };
    #pragma unroll
    for (int s = 0; s < 2; s++) {
        if (s < NK) load(s, s * 16);
        CP_COMMIT();
    }
    for (int i = 0; i < NK; i++) {
        CP_WAIT1();
        __syncthreads();
        if (i + 2 < NK) load((i + 2) % 3, (i + 2) * 16);
        CP_COMMIT();
        int st = i % 3;
        unsigned aA = aAq + st * ASTG;
        unsigned aB = aBq + st * BSTG;
        #pragma unroll
        for (int t = 0; t < 3; t++) {
            unsigned a[3][4], b[2][4];
            #pragma unroll
            for (int mt = 0; mt < 3; mt++)
                ldsm4(a[mt][0], a[mt][1], a[mt][2], a[mt][3],
                      aA + ((t * 96 + mt * 16) * 24) * 2);
            #pragma unroll
            for (int np = 0; np < 2; np++)
                ldsm4(b[np][0], b[np][1], b[np][2], b[np][3],
                      aB + ((t + np * 16) * 24) * 2);
            #pragma unroll
            for (int mt = 0; mt < 3; mt++)
                #pragma unroll
                for (int nt = 0; nt < 4; nt++)
                    MMA_FP16(acc[mt][nt], a[mt],
                             b[nt >> 1][(nt & 1) * 2], b[nt >> 1][(nt & 1) * 2 + 1]);
        }
    }

    #pragma unroll
    for (int mt = 0; mt < 3; mt++) {
        #pragma unroll
        for (int half_ = 0; half_ < 2; half_++) {
            int gm = bm + mbase + mt * 16 + (lane >> 2) + half_ * 8;
            if (gm < PRED) {
                float s  = bg[gm] * rsqrtf(bv[gm] + EPSBN);
                float sht = bb[gm] - bmn[gm] * s;
                float cv = cb[gm];
                #pragma unroll
                for (int nt = 0; nt < 4; nt++) {
                    int gn0 = bn + nbase + nt * 8 + (lane & 3) * 2;
                    float y0 = fmaxf(acc[mt][nt][half_ * 2]     + cv, 0.f);
                    float y1 = fmaxf(acc[mt][nt][half_ * 2 + 1] + cv, 0.f);
                    float v0 = rnd(y0 * s + sht), v1 = rnd(y1 * s + sht);
                    if (OutT) {
                        OutT[((long)b * POSE + gn0)     * 192 + gm] = __float2half_rn(v0);
                        OutT[((long)b * POSE + gn0 + 1) * 192 + gm] = __float2half_rn(v1);
                    } else {
                        long o = ((long)b * PRED + gm) * POSE + gn0;
                        *(__half2*)(OutH + o) = __halves2half2(__float2half_rn(v0),
                                                               __float2half_rn(v1));
                    }
                }
            }
        }
    }
}

// ---------------------------------------------------------------------------
// fp16 final GEMM (R11-proven): CTA 128x256, warp 64x64, K-slab 32, 4-stage.
// ---------------------------------------------------------------------------
__global__ __launch_bounds__(256)
void final_hp(const __half* __restrict__ xf, const __half* __restrict__ pf,
              const __half* __restrict__ Wf, const float* __restrict__ bias,
              float* __restrict__ C)
{
    extern __shared__ unsigned sh[];
    __shared__ const __half* rowp[128];
    unsigned shbase = s2u(sh);
    const unsigned ASTG = 128u * 40u * 2u;
    const unsigned BSTG = 256u * 40u * 2u;
    const unsigned bsoff = 4u * ASTG;

    const int tid = threadIdx.x;
    const int warpid = tid >> 5, lane = tid & 31;
    const int mbase = (warpid >> 2) * 64, nbase = (warpid & 3) * 64;
    const int quad = lane >> 3, qr = lane & 7;
    const int bm = blockIdx.y * 128, bn = blockIdx.x * 256;
    const int nk = POSE / 32;

    if (tid < 128) {
        int r = bm + tid;
        int bb_ = r / FRAMES, f = r - bb_ * FRAMES;
        rowp[tid] = (f < PRIOR) ? xf + ((long)bb_ * PRIOR + f) * POSE
                                : pf + ((long)bb_ * PRED + (f - PRIOR)) * POSE;
    }
    __syncthreads();

    const unsigned aAq = shbase + (((mbase + (quad & 1) * 8 + qr) * 40 + (quad >> 1) * 8) * 2);
    const unsigned aBq = shbase + bsoff + (((nbase + (quad >> 1) * 8 + qr) * 40 + (quad & 1) * 8) * 2);

    float acc[4][8][4];
    #pragma unroll
    for (int mt = 0; mt < 4; mt++)
        #pragma unroll
        for (int nt = 0; nt < 8; nt++)
            #pragma unroll
            for (int r = 0; r < 4; r++) acc[mt][nt][r] = 0.f;

    const int m_ = tid >> 2, kq = tid & 3;
    auto load = [&](int st, int k0) {
        int gk = k0 + kq * 8;
        #pragma unroll
        for (int i = 0; i < 2; i++) {
            int m = m_ + i * 64;
            cp16(shbase + st * ASTG + (m * 40 + kq * 8) * 2, rowp[m] + gk, true);
        }
        #pragma unroll
        for (int i = 0; i < 4; i++) {
            int n = m_ + i * 64;
            cp16(shbase + bsoff + st * BSTG + (n * 40 + kq * 8) * 2,
                 Wf + (long)(bn + n) * POSE + gk, true);
        }
    };

    #pragma unroll
    for (int s = 0; s < 3; s++) { load(s, s * 32); CP_COMMIT(); }
    for (int i = 0; i < nk; i++) {
        CP_WAIT2();
        __syncthreads();
        if (i + 3 < nk) load((i + 3) & 3, (i + 3) * 32);
        CP_COMMIT();
        int st = i & 3;
        unsigned aA = aAq + st * ASTG, aB = aBq + st * BSTG;
        #pragma unroll
        for (int kh = 0; kh < 2; kh++) {
            unsigned a[4][4], b[4][4];
            #pragma unroll
            for (int mt = 0; mt < 4; mt++)
                ldsm4(a[mt][0], a[mt][1], a[mt][2], a[mt][3],
                      aA + (mt * 16 * 40 + kh * 16) * 2);
            #pragma unroll
            for (int np = 0; np < 4; np++)
                ldsm4(b[np][0], b[np][1], b[np][2], b[np][3],
                      aB + (np * 16 * 40 + kh * 16) * 2);
            #pragma unroll
            for (int mt = 0; mt < 4; mt++)
                #pragma unroll
                for (int nt = 0; nt < 8; nt++)
                    MMA_FP16(acc[mt][nt], a[mt],
                             b[nt >> 1][(nt & 1) * 2], b[nt >> 1][(nt & 1) * 2 + 1]);
        }
    }

    #pragma unroll
    for (int mt = 0; mt < 4; mt++) {
        int gm0 = bm + mbase + mt * 16 + (lane >> 2);
        #pragma unroll
        for (int nt = 0; nt < 8; nt++) {
            int gn0 = bn + nbase + nt * 8 + (lane & 3) * 2;
            float2 bv = *(const float2*)(bias + gn0);
            float2 v0 = make_float2(acc[mt][nt][0] + bv.x, acc[mt][nt][1] + bv.y);
            float2 v1 = make_float2(acc[mt][nt][2] + bv.x, acc[mt][nt][3] + bv.y);
            *(float2*)(C + (long)gm0 * POSE + gn0)       = v0;
            *(float2*)(C + (long)(gm0 + 8) * POSE + gn0) = v1;
        }
    }
}

// ---------------- prep / glue ----------------
struct R5 { const float4* s[5]; __half2* d[5]; int n4[5]; };
__global__ void k_round_h(R5 r, int total4)
{
    int gid = blockIdx.x * blockDim.x + threadIdx.x;
    if (gid >= total4) return;
    #pragma unroll
    for (int k = 0; k < 5; k++) {
        if (gid < r.n4[k]) {
            float4 v = r.s[k][gid];
            r.d[k][gid * 2]     = __halves2half2(__float2half_rn(rnd(v.x)),
                                                 __float2half_rn(rnd(v.y)));
            r.d[k][gid * 2 + 1] = __halves2half2(__float2half_rn(rnd(v.z)),
                                                 __float2half_rn(rnd(v.w)));
            return;
        }
        gid -= r.n4[k];
    }
}

// x [b][60][768] -> xT fp16 [b][768][64] AND xf fp16 [b][60][768];
// also zero p1T pad cols 180-191.
__global__ void k_trx(const float* __restrict__ x, __half* __restrict__ xT,
                      __half* __restrict__ xf, __half* __restrict__ p1T)
{
    __shared__ float t[64][33];
    int b = blockIdx.y, pos0 = blockIdx.x * 32;
    int tx = threadIdx.x, ty = threadIdx.y;
    for (int ich = ty; ich < 64; ich += 8) {
        float v = (ich < PRIOR) ? rnd(x[((long)b * PRIOR + ich) * POSE + pos0 + tx]) : 0.f;
        t[ich][tx] = v;
        if (ich < PRIOR)
            xf[((long)b * PRIOR + ich) * POSE + pos0 + tx] = __float2half_rn(v);
    }
    __syncthreads();
    int tid = ty * 32 + tx;
    for (int e = tid; e < 32 * 64; e += 256) {
        int r = e >> 6, ich = e & 63;
        xT[((long)b * POSE + pos0 + r) * 64 + ich] = __float2half_rn(t[ich][r]);
    }
    for (int e = tid; e < 32 * 12; e += 256) {
        int r = e / 12, j = e - r * 12;
        p1T[((long)b * POSE + pos0 + r) * 192 + 180 + j] = __float2half_rn(0.f);
    }
}

__global__ void k_convw(const float* __restrict__ w1, const float* __restrict__ w2,
                        __half* __restrict__ Wr1, __half* __restrict__ Wr2)
{
    const int N1 = 3 * 192 * 64, N2 = 3 * 192 * 192;
    int t = blockIdx.x * blockDim.x + threadIdx.x;
    if (t < N1) {
        int tap = t / (192 * 64), rem = t % (192 * 64);
        int o = rem / 64, ich = rem % 64;
        float v = 0.f;
        if (o < PRED && ich < PRIOR) v = rnd(w1[(o * PRIOR + ich) * 3 + tap]);
        Wr1[t] = __float2half_rn(v);
    } else if (t < N1 + N2) {
        t -= N1;
        int tap = t / (192 * 192), rem = t % (192 * 192);
        int o = rem / 192, ich = rem % 192;
        float v = 0.f;
        if (o < PRED && ich < PRED) v = rnd(w2[(o * PRED + ich) * 3 + tap]);
        Wr2[t] = __float2half_rn(v);
    }
}

__global__ void k_trT(const float* __restrict__ s, __half* __restrict__ d)
{
    __shared__ float t[32][33];
    int x0 = blockIdx.x * 32, y0 = blockIdx.y * 32;
    for (int i = threadIdx.y; i < 32; i += 8)
        t[i][threadIdx.x] = s[(long)(y0 + i) * POSE + x0 + threadIdx.x];
    __syncthreads();
    for (int i = threadIdx.y; i < 32; i += 8)
        d[(long)(x0 + i) * POSE + y0 + threadIdx.x] = __float2half_rn(rnd(t[threadIdx.x][i]));
}

__global__ void reduce2(const float* __restrict__ part, int S,
                        const float* __restrict__ ba, const float* __restrict__ bb,
                        float* __restrict__ oa, float* __restrict__ ob,
                        __half* __restrict__ oah, __half* __restrict__ obh)
{
    const int MN = BSZ * 1536;
    int i = blockIdx.x * blockDim.x + threadIdx.x;
    if (i >= MN) return;
    float s = 0.f;
    for (int z = 0; z < S; z++) s += part[(long)z * MN + i];
    int m = i / 1536, n = i - m * 1536;
    if (n < 768) {
        s += ba[n];
        if (oa)  oa[m * 768 + n] = s;
        if (oah) oah[m * 768 + n] = __float2half_rn(rnd(s));
    } else {
        int nn = n - 768;
        s += bb[nn];
        if (ob)  ob[m * 768 + nn] = s;
        if (obh) obh[m * 768 + nn] = __float2half_rn(rnd(s));
    }
}

__global__ void reduce_wch(const float* __restrict__ part,
                           __half* __restrict__ Wf, int MN, int S)
{
    int i = blockIdx.x * blockDim.x + threadIdx.x;
    if (i >= MN) return;
    float s = 0.f;
    for (int z = 0; z < S; z++) s += part[(long)z * MN + i];
    Wf[i] = __float2half_rn(rnd(s));
}

__global__ void k_bc(const float* __restrict__ w2, const float* __restrict__ b1,
                     const float* __restrict__ b2, float* __restrict__ bc)
{
    int w = (blockIdx.x * blockDim.x + threadIdx.x) >> 5;
    int lane = threadIdx.x & 31;
    if (w >= POSE) return;
    float s = 0.f;
    for (int m = lane; m < POSE; m += 32) s += w2[(long)w * POSE + m] * b1[m];
    s = warp_sum(s);
    if (lane == 0) bc[w] = s + b2[w];
}

__global__ void k_tmm(const float* __restrict__ w1, const float* __restrict__ b1,
                      const float* __restrict__ w2, const float* __restrict__ b2,
                      float* __restrict__ Wt, float* __restrict__ bt)
{
    int idx = blockIdx.x * blockDim.x + threadIdx.x;
    const int KK = CHUNK * POSE;
    if (idx < CHUNK * KK) {
        int c = idx / KK, k = idx - c * KK;
        float s = 0.f;
        #pragma unroll
        for (int m = 0; m < CHUNK; m++) s += w2[c * CHUNK + m] * w1[(long)m * KK + k];
        Wt[idx] = s;
    }
    if (idx < CHUNK) {
        float s = b2[idx];
        #pragma unroll
        for (int m = 0; m < CHUNK; m++) s += w2[idx * CHUNK + m] * b1[m];
        bt[idx] = s;
    }
}

__global__ __launch_bounds__(320)
void gate_penc(const __half* __restrict__ pf, const float* __restrict__ mem,
               const float* __restrict__ Wt, const float* __restrict__ bt,
               float* __restrict__ pch, float* __restrict__ penc)
{
    __shared__ float sm[POSE];
    __shared__ float chunk[CHUNK * POSE];
    __shared__ float sig[CHUNK];
    const int b = blockIdx.x, t = threadIdx.x;
    const __half* pfb = pf + (long)b * PRED * POSE;
    for (int i = t; i < POSE; i += 320) sm[i] = mem[(long)b * POSE + i];
    for (int i = t; i < CHUNK * POSE; i += 320) chunk[i] = __half2float(pfb[i]);
    __syncthreads();
    const int w = t >> 5, lane = t & 31;
    float s = 0.f;
    for (int d = lane; d < POSE; d += 32) s += sm[d] * chunk[w * POSE + d];
    s = warp_sum(s);
    if (lane == 0) sig[w] = 1.f / (1.f + expf(-s));
    __syncthreads();
    float* pcb = pch + (long)b * CHUNK * POSE;
    for (int i = t; i < CHUNK * POSE; i += 320) {
        int c = i / POSE, d = i - c * POSE;
        float g = sig[c];
        chunk[i] = g * chunk[i] + (1.f - g) * sm[d];
        pcb[i] = rnd(chunk[i]);
    }
    __syncthreads();
    float acc = 0.f;
    for (int k = lane; k < CHUNK * POSE; k += 32) acc += chunk[k] * Wt[(long)w * CHUNK * POSE + k];
    acc = warp_sum(acc);
    if (lane == 0) penc[b * CHUNK + w] = acc + bt[w];
}

__global__ void k_M(const float* __restrict__ mem2, const float* __restrict__ penc,
                    float* __restrict__ Mo)
{
    __shared__ float pe[BSZ * CHUNK];
    const int t = threadIdx.x;
    for (int i = t; i < BSZ * CHUNK; i += 256) pe[i] = penc[i];
    __syncthreads();
    int d = blockIdx.x * 256 + t;
    float acc[CHUNK];
    #pragma unroll
    for (int c = 0; c < CHUNK; c++) acc[c] = 0.f;
    for (int b = 0; b < BSZ; b++) {
        float mv = mem2[(long)b * POSE + d];
        #pragma unroll
        for (int c = 0; c < CHUNK; c++) acc[c] = fmaf(mv, pe[b * CHUNK + c], acc[c]);
    }
    #pragma unroll
    for (int c = 0; c < CHUNK; c++) Mo[d * CHUNK + c] = acc[c];
}

__global__ __launch_bounds__(320)
void k_score2(const float* __restrict__ pch, const float* __restrict__ mem2,
              const float* __restrict__ Mo, __half* __restrict__ pf)
{
    __shared__ float sm[POSE];
    __shared__ float sc[CHUNK];
    __shared__ float softs[CHUNK];
    const int b = blockIdx.x, t = threadIdx.x;
    for (int i = t; i < POSE; i += 320) sm[i] = mem2[(long)b * POSE + i];
    __syncthreads();
    const int w = t >> 5, lane = t & 31;
    float s = 0.f;
    for (int d = lane; d < POSE; d += 32) s += sm[d] * Mo[d * CHUNK + w];
    s = warp_sum(s);
    if (lane == 0) sc[w] = s;
    __syncthreads();
    if (t == 0) {
        float mx = sc[0];
        #pragma unroll
        for (int c = 1; c < CHUNK; c++) mx = fmaxf(mx, sc[c]);
        float ssum = 0.f;
        #pragma unroll
        for (int c = 0; c < CHUNK; c++) { float e = expf(sc[c] - mx); softs[c] = e; ssum += e; }
        float inv = 1.f / ssum;
        #pragma unroll
        for (int c = 0; c < CHUNK; c++) softs[c] *= inv;
    }
    __syncthreads();
    const float* pcb = pch + (long)b * CHUNK * POSE;
    __half* pfb = pf + (long)b * PRED * POSE;
    for (int i = t; i < CHUNK * POSE; i += 320) {
        int c = i / POSE;
        pfb[i] = __float2half_rn(rnd(pcb[i] * (1.f + softs[c])));
    }
}

// ---------------- launch ----------------
extern "C" void kernel_launch(void* const* d_in, const int* in_sizes, int n_in,
                              void* d_out, int out_size)
{
    const float* x       = (const float*)d_in[0];
    const float* conv1_w = (const float*)d_in[1];
    const float* conv1_b = (const float*)d_in[2];
    const float* bn1_g   = (const float*)d_in[3];
    const float* bn1_b   = (const float*)d_in[4];
    const float* bn1_m   = (const float*)d_in[5];
    const float* bn1_v   = (const float*)d_in[6];
    const float* conv2_w = (const float*)d_in[7];
    const float* conv2_b = (const float*)d_in[8];
    const float* bn2_g   = (const float*)d_in[9];
    const float* bn2_b   = (const float*)d_in[10];
    const float* bn2_m   = (const float*)d_in[11];
    const float* bn2_v   = (const float*)d_in[12];
    const float* sp_w1   = (const float*)d_in[13];
    const float* sp_b1   = (const float*)d_in[14];
    const float* sp_w2   = (const float*)d_in[15];
    const float* sp_b2   = (const float*)d_in[16];
    const float* tmc_w1  = (const float*)d_in[17];
    const float* tmc_b1  = (const float*)d_in[18];
    const float* tmc_w2  = (const float*)d_in[19];
    const float* tmc_b2  = (const float*)d_in[20];
    const float* tmm_w1  = (const float*)d_in[21];
    const float* tmm_b1  = (const float*)d_in[22];
    const float* tmm_w2  = (const float*)d_in[23];
    const float* tmm_b2  = (const float*)d_in[24];
    const float* post_w1 = (const float*)d_in[25];
    const float* post_b1 = (const float*)d_in[26];
    const float* post_w2 = (const float*)d_in[27];
    const float* post_b2 = (const float*)d_in[28];

    float *pch, *bc, *Wt, *bt, *mem, *mem2, *penc, *Mm, *part;
    __half *p1T, *xT, *wr1, *wr2, *w1cat, *sw2, *tw2, *pw2, *pw1T;
    __half *hsp, *htm, *xf, *pf, *Wcf;
    cudaGetSymbolAddress((void**)&pch,   g_pch);
    cudaGetSymbolAddress((void**)&p1T,   g_p1T);
    cudaGetSymbolAddress((void**)&xT,    g_xT);
    cudaGetSymbolAddress((void**)&wr1,   g_wr1);
    cudaGetSymbolAddress((void**)&wr2,   g_wr2);
    cudaGetSymbolAddress((void**)&w1cat, g_w1cat);
    cudaGetSymbolAddress((void**)&sw2,   g_sw2);
    cudaGetSymbolAddress((void**)&tw2,   g_tw2);
    cudaGetSymbolAddress((void**)&pw2,   g_pw2);
    cudaGetSymbolAddress((void**)&pw1T,  g_pw1T);
    cudaGetSymbolAddress((void**)&bc,    g_bc);
    cudaGetSymbolAddress((void**)&Wt,    g_Wt);
    cudaGetSymbolAddress((void**)&bt,    g_bt);
    cudaGetSymbolAddress((void**)&hsp,   g_hsp);
    cudaGetSymbolAddress((void**)&htm,   g_htm);
    cudaGetSymbolAddress((void**)&mem,   g_mem);
    cudaGetSymbolAddress((void**)&mem2,  g_mem2);
    cudaGetSymbolAddress((void**)&penc,  g_penc);
    cudaGetSymbolAddress((void**)&Mm,    g_Mmat);
    cudaGetSymbolAddress((void**)&part,  g_part);
    cudaGetSymbolAddress((void**)&xf,    g_xf);
    cudaGetSymbolAddress((void**)&pf,    g_pf);
    cudaGetSymbolAddress((void**)&Wcf,   g_Wcf);

    const int SMEM_G    = 4 * 128 * 40 * 2 * 2;                // 81920
    const int SMEM_CONV = 3 * (288 * 24 + 136 * 24) * 2;       // 61056
    const int SMEM_HP   = 4 * (128 * 40 + 256 * 40) * 2;       // 122880
    cudaFuncSetAttribute(ghemm,        cudaFuncAttributeMaxDynamicSharedMemorySize, SMEM_G);
    cudaFuncSetAttribute(final_hp,     cudaFuncAttributeMaxDynamicSharedMemorySize, SMEM_HP);
    cudaFuncSetAttribute(conv_hp<60>,  cudaFuncAttributeMaxDynamicSharedMemorySize, SMEM_CONV);
    cudaFuncSetAttribute(conv_hp<180>, cudaFuncAttributeMaxDynamicSharedMemorySize, SMEM_CONV);

    // 0,1: conv prep (k_trx also emits xf)
    k_convw<<<(3*192*64 + 3*192*192 + 255) / 256, 256>>>(conv1_w, conv2_w, wr1, wr2);
    k_trx<<<dim3(24, BSZ), dim3(32, 8)>>>(x, xT, xf, p1T);

    // 2: conv1 (-> p1T)   3: conv2 (-> pf), ncu capture idx 3
    conv_hp<60><<<dim3(6, 2, BSZ), 256, SMEM_CONV>>>(xT, wr1, conv1_b,
        bn1_g, bn1_b, bn1_m, bn1_v, nullptr, p1T);
    conv_hp<180><<<dim3(6, 2, BSZ), 256, SMEM_CONV>>>(p1T, wr2, conv2_b,
        bn2_g, bn2_b, bn2_m, bn2_v, pf, nullptr);

    // 4: fp16 round-copies of remaining GEMM operands (x handled by k_trx)
    R5 r;
    const float* srcs[5] = { sp_w1, tmc_w1, sp_w2, tmc_w2, post_w2 };
    __half* dsts[5]      = { w1cat, w1cat + POSE * CHUNK * POSE, sw2, tw2, pw2 };
    int ns[5] = { POSE*CHUNK*POSE, POSE*CHUNK*POSE, POSE*POSE, POSE*POSE, POSE*POSE };
    int total4 = 0;
    for (int i = 0; i < 5; i++) {
        r.s[i] = (const float4*)srcs[i]; r.d[i] = (__half2*)dsts[i];
        r.n4[i] = ns[i] / 4; total4 += ns[i] / 4;
    }
    k_round_h<<<(total4 + 255) / 256, 256>>>(r, total4);

    // 5-7: small weight prep
    k_trT<<<dim3(24, 24), dim3(32, 8)>>>(post_w1, pw1T);
    k_bc<<<96, 256>>>(post_w2, post_b1, post_b2, bc);
    k_tmm<<<300, 256>>>(tmm_w1, tmm_b1, tmm_w2, tmm_b2, Wt, bt);

    // 8,9: merged SP/TMC layer-1 (fp16, split-K 16)
    const __half* tail = xf + (PRIOR - CHUNK) * POSE;
    ghemm<<<dim3(12, 2, 16), 256, SMEM_G>>>(tail, (long)PRIOR * POSE, w1cat,
        (long)CHUNK * POSE, part, BSZ, 2 * POSE, CHUNK * POSE, 480, 1536, 0);
    reduce2<<<(BSZ * 1536 + 255) / 256, 256>>>(part, 16, sp_b1, tmc_b1,
        nullptr, nullptr, hsp, htm);
    // 10-12: layer-2 (fp16)
    ghemm<<<dim3(6, 2, 8), 256, SMEM_G>>>(hsp, POSE, sw2, POSE,
        part, BSZ, POSE, POSE, 96, 1536, 0);
    ghemm<<<dim3(6, 2, 8), 256, SMEM_G>>>(htm, POSE, tw2, POSE,
        part, BSZ, POSE, POSE, 96, 1536, 768);
    reduce2<<<(BSZ * 1536 + 255) / 256, 256>>>(part, 8, sp_b2, tmc_b2,
        mem, mem2, nullptr, nullptr);

    // 13,14: Wc = post_w2 @ post_w1 (fp16) -> Wcf
    ghemm<<<dim3(6, 6, 8), 256, SMEM_G>>>(pw2, POSE, pw1T, POSE,
        part, POSE, POSE, POSE, 96, POSE, 0);
    reduce_wch<<<(POSE * POSE + 255) / 256, 256>>>(part, Wcf, POSE * POSE, 8);

    // 15-17: memory nets
    gate_penc<<<BSZ, 320>>>(pf, mem, Wt, bt, pch, penc);
    k_M<<<3, 256>>>(mem2, penc, Mm);
    k_score2<<<BSZ, 320>>>(pch, mem2, Mm, pf);

    // 18: fp16 final GEMM -> d_out
    final_hp<<<dim3(3, 480), 256, SMEM_HP>>>(xf, pf, Wcf, bc, (float*)d_out);
}